// round 11
// baseline (speedup 1.0000x reference)
#include <cuda_runtime.h>
#include <cuda_bf16.h>
#include <math.h>
#include <stdint.h>

#define Bsz 8
#define Tn 256
#define Dm 1024
#define Nn 2048
#define MS_W 5120
#define HM 16
#define DH 64
#define HG 8
#define GD 128

// ===================== portable PTX helpers (compute_103-safe) ==============
__device__ __forceinline__ uint32_t smem_u32(const void* p) {
    uint32_t a;
    asm("{ .reg .u64 t; cvta.to.shared.u64 t, %1; cvt.u32.u64 %0, t; }" : "=r"(a) : "l"(p));
    return a;
}
#define SMEM_SWZ128(x) ((x) ^ (((x) >> 3) & 0x70))

__device__ __forceinline__ void cp16(uint32_t dst, const void* src, int sz) {
    asm volatile("cp.async.cg.shared.global [%0], [%1], 16, %2;" ::"r"(dst), "l"(src), "r"(sz));
}
#define CP_COMMIT() asm volatile("cp.async.commit_group;" ::: "memory")
#define CP_WAIT1() asm volatile("cp.async.wait_group 1;" ::: "memory")
#define CP_WAIT0() asm volatile("cp.async.wait_group 0;" ::: "memory")

__device__ __forceinline__ void ldsm4(uint32_t& r0, uint32_t& r1, uint32_t& r2, uint32_t& r3,
                                      uint32_t a) {
    asm volatile("ldmatrix.sync.aligned.m8n8.x4.shared.b16 {%0,%1,%2,%3}, [%4];"
                 : "=r"(r0), "=r"(r1), "=r"(r2), "=r"(r3) : "r"(a));
}
__device__ __forceinline__ void mma16816(float* d, const uint32_t* a, const uint32_t* b) {
    asm volatile(
        "mma.sync.aligned.m16n8k16.row.col.f32.bf16.bf16.f32 "
        "{%0,%1,%2,%3}, {%4,%5,%6,%7}, {%8,%9}, {%0,%1,%2,%3};"
        : "+f"(d[0]), "+f"(d[1]), "+f"(d[2]), "+f"(d[3])
        : "r"(a[0]), "r"(a[1]), "r"(a[2]), "r"(a[3]), "r"(b[0]), "r"(b[1]));
}

// ===================== scratch =============================================
__device__ __align__(16) __nv_bfloat16 g_x3[(size_t)Nn * 3072];
__device__ __align__(16) __nv_bfloat16 g_ms3[(size_t)Nn * 15360];
__device__ __align__(16) __nv_bfloat16 g_z3[(size_t)Nn * 3072];
__device__ __align__(16) __nv_bfloat16 g_q3[(size_t)Nn * 3072];
__device__ __align__(16) __nv_bfloat16 g_k3[(size_t)Nn * 3072];
__device__ __align__(16) __nv_bfloat16 g_ctx3[(size_t)Nn * 3072];
__device__ __align__(16) __nv_bfloat16 g_att3[(size_t)Nn * 3072];
__device__ __align__(16) __nv_bfloat16 g_attn3[(size_t)Bsz * HM * Tn * 768];
__device__ __align__(16) __nv_bfloat16 g_vt3[(size_t)Bsz * HM * DH * 768];
__device__ __align__(16) __nv_bfloat16 g_wc3[(size_t)5 * 1024 * 21504];
__device__ __align__(16) __nv_bfloat16 g_fpw3[(size_t)1024 * 15360];
__device__ __align__(16) __nv_bfloat16 g_wq3[(size_t)1024 * 3072];
__device__ __align__(16) __nv_bfloat16 g_wk3[(size_t)1024 * 3072];
__device__ __align__(16) __nv_bfloat16 g_wv3[(size_t)1024 * 3072];
__device__ __align__(16) __nv_bfloat16 g_wo3[(size_t)1024 * 3072];
__device__ __align__(16) __nv_bfloat16 g_gw3[(size_t)1024 * 3072];

__device__ float g_zpre[(size_t)Nn * Dm];
__device__ float g_v[(size_t)Nn * Dm];
__device__ float g_scores[(size_t)Bsz * HM * Tn * Tn];
__device__ float g_ctx[(size_t)Nn * Dm];
__device__ float g_hg[(size_t)Nn * Dm];
__device__ float g_e1[Nn * HG];
__device__ float g_e2[Nn * HG];
__device__ float g_e2max[HG];

__constant__ int c_dils[5] = {1, 2, 4, 8, 16};

// ===================== split conversions ====================================
__global__ void __launch_bounds__(256) split_mat(const float* __restrict__ in,
                                                 __nv_bfloat16* __restrict__ out,
                                                 int Cd, int patB) {
    int r = blockIdx.x;
    size_t ib = (size_t)r * Cd, ob = (size_t)r * 3 * Cd;
    for (int c = threadIdx.x; c < Cd; c += 256) {
        float x = in[ib + c];
        __nv_bfloat16 h = __float2bfloat16(x);
        __nv_bfloat16 l = __float2bfloat16(x - __bfloat162float(h));
        if (patB) { out[ob + c] = h; out[ob + Cd + c] = h; out[ob + 2 * Cd + c] = l; }
        else      { out[ob + c] = h; out[ob + Cd + c] = l; out[ob + 2 * Cd + c] = h; }
    }
}

// conv weight w[o][i][k] -> wc3[o][kk*3072 + {i:hi, 1024+i:hi, 2048+i:lo}]
__global__ void __launch_bounds__(256) split_conv_w(const float* __restrict__ w,
                                                    __nv_bfloat16* __restrict__ out) {
    int o = blockIdx.x;
    for (int i = threadIdx.x; i < 1024; i += 256) {
#pragma unroll
        for (int kk = 0; kk < 7; ++kk) {
            float x = w[(size_t)o * 7168 + i * 7 + kk];
            __nv_bfloat16 h = __float2bfloat16(x);
            __nv_bfloat16 l = __float2bfloat16(x - __bfloat162float(h));
            size_t base = (size_t)o * 21504 + kk * 3072;
            out[base + i] = h; out[base + 1024 + i] = h; out[base + 2048 + i] = l;
        }
    }
}

// ===================== warp-MMA compute core ================================
// smem stage: A tile (rows x 64k bf16, swizzled 128B rows) at sA, B tile at sB.
__device__ __forceinline__ void mma_stage(uint32_t sA, uint32_t sB, int warp_m, int warp_n,
                                          int lane, float acc[4][4][4]) {
    int lrow = lane & 15;
    int lcol = (lane >> 4) * 16;
#pragma unroll
    for (int ks = 0; ks < 4; ++ks) {
        uint32_t a[4][4];
        uint32_t b[4][2];
#pragma unroll
        for (int mi = 0; mi < 4; ++mi) {
            int row = warp_m * 64 + mi * 16 + lrow;
            uint32_t addr = sA + SMEM_SWZ128(row * 128 + ks * 32 + lcol);
            ldsm4(a[mi][0], a[mi][1], a[mi][2], a[mi][3], addr);
        }
#pragma unroll
        for (int nj = 0; nj < 2; ++nj) {
            int row = warp_n * 32 + nj * 16 + lrow;
            uint32_t addr = sB + SMEM_SWZ128(row * 128 + ks * 32 + lcol);
            uint32_t r0, r1, r2, r3;
            ldsm4(r0, r1, r2, r3, addr);
            b[nj * 2][0] = r0;     b[nj * 2][1] = r2;
            b[nj * 2 + 1][0] = r1; b[nj * 2 + 1][1] = r3;
        }
#pragma unroll
        for (int mi = 0; mi < 4; ++mi)
#pragma unroll
            for (int ni = 0; ni < 4; ++ni)
                mma16816(acc[mi][ni], a[mi], b[ni]);
    }
}

// ===================== conv GEMM (implicit shift, K'=21504) =================
__global__ void __launch_bounds__(256) conv_tc(
    const __nv_bfloat16* __restrict__ x3, const __nv_bfloat16* __restrict__ wc3,
    const float* __restrict__ b0, const float* __restrict__ b1,
    const float* __restrict__ b2, const float* __restrict__ b3,
    const float* __restrict__ b4, __nv_bfloat16* __restrict__ ms3) {
    extern __shared__ __align__(16) char smem[];
    uint32_t sb = smem_u32(smem);
    int tid = threadIdx.x, wid = tid >> 5, lane = tid & 31;
    int warp_m = wid >> 2, warp_n = wid & 3;
    int n0 = blockIdx.x * 128, m0 = blockIdx.y * 128;
    int dz = blockIdx.z, dil = c_dils[dz];
    const __nv_bfloat16* B3 = wc3 + (size_t)dz * 1024 * 21504;
    int seqbase = m0 & ~255, trow0 = m0 & 255;
    int ar = tid >> 3, ac = tid & 7;

    float acc[4][4][4] = {};
    const int nch = 21504 / 64;   // 336

#define CONV_LOAD(it, stg) do {                                                            \
        int k0 = (it) << 6;                                                                \
        int kk = k0 / 3072;                                                                \
        int inner0 = k0 - kk * 3072;                                                       \
        int shift = (kk - 3) * dil;                                                        \
        uint32_t abase = sb + (uint32_t)(stg) * 32768u;                                    \
        uint32_t bbase = abase + 16384u;                                                   \
        _Pragma("unroll")                                                                  \
        for (int rr = 0; rr < 4; ++rr) {                                                   \
            int r = ar + rr * 32;                                                          \
            int t = trow0 + r + shift;                                                     \
            int ok = ((unsigned)t < 256u) ? 16 : 0;                                        \
            int tc2 = ok ? t : 0;                                                          \
            cp16(abase + SMEM_SWZ128(r * 128 + ac * 16),                                   \
                 x3 + (size_t)(seqbase + tc2) * 3072 + inner0 + ac * 8, ok);               \
            cp16(bbase + SMEM_SWZ128(r * 128 + ac * 16),                                   \
                 B3 + (size_t)(n0 + r) * 21504 + k0 + ac * 8, 16);                         \
        }                                                                                  \
        CP_COMMIT();                                                                       \
    } while (0)

    CONV_LOAD(0, 0);
    CONV_LOAD(1, 1);
    for (int it = 0; it < nch; ++it) {
        int stg = it % 3;
        if (it + 1 < nch) CP_WAIT1(); else CP_WAIT0();
        __syncthreads();
        if (it + 2 < nch) CONV_LOAD(it + 2, (it + 2) % 3);
        mma_stage(sb + (uint32_t)stg * 32768u, sb + (uint32_t)stg * 32768u + 16384u,
                  warp_m, warp_n, lane, acc);
    }
#undef CONV_LOAD

    const float* bias = dz == 0 ? b0 : dz == 1 ? b1 : dz == 2 ? b2 : dz == 3 ? b3 : b4;
    int lr = lane >> 2, lc = (lane & 3) * 2;
#pragma unroll
    for (int mi = 0; mi < 4; ++mi)
#pragma unroll
        for (int ni = 0; ni < 4; ++ni)
#pragma unroll
            for (int e = 0; e < 4; ++e) {
                int m = m0 + warp_m * 64 + mi * 16 + lr + ((e >> 1) ? 8 : 0);
                int n = n0 + warp_n * 32 + ni * 8 + lc + (e & 1);
                float v = acc[mi][ni][e] + bias[n];
                __nv_bfloat16 h = __float2bfloat16(v);
                __nv_bfloat16 l = __float2bfloat16(v - __bfloat162float(h));
                size_t rbase = (size_t)m * 15360;
                size_t col = (size_t)dz * 1024 + n;
                ms3[rbase + col] = h;
                ms3[rbase + 5120 + col] = l;
                ms3[rbase + 10240 + col] = h;
            }
}

// ===================== dense GEMM: C = A3 . B3^T + bias =====================
// C3 != null: bf16 triple out (patB selects [hi|hi|lo] vs [hi|lo|hi]); else fp32.
__global__ void __launch_bounds__(256) dense_tc(
    const __nv_bfloat16* __restrict__ A3, const __nv_bfloat16* __restrict__ B3,
    const float* __restrict__ bias, float* __restrict__ Cf,
    __nv_bfloat16* __restrict__ C3, int Kp, int patB) {
    extern __shared__ __align__(16) char smem[];
    uint32_t sb = smem_u32(smem);
    int tid = threadIdx.x, wid = tid >> 5, lane = tid & 31;
    int warp_m = wid >> 2, warp_n = wid & 3;
    int n0 = blockIdx.x * 128, m0 = blockIdx.y * 128;
    int ar = tid >> 3, ac = tid & 7;

    float acc[4][4][4] = {};
    int nch = Kp >> 6;

#define DENSE_LOAD(it, stg) do {                                                           \
        int k0 = (it) << 6;                                                                \
        uint32_t abase = sb + (uint32_t)(stg) * 32768u;                                    \
        uint32_t bbase = abase + 16384u;                                                   \
        _Pragma("unroll")                                                                  \
        for (int rr = 0; rr < 4; ++rr) {                                                   \
            int r = ar + rr * 32;                                                          \
            cp16(abase + SMEM_SWZ128(r * 128 + ac * 16),                                   \
                 A3 + (size_t)(m0 + r) * Kp + k0 + ac * 8, 16);                            \
            cp16(bbase + SMEM_SWZ128(r * 128 + ac * 16),                                   \
                 B3 + (size_t)(n0 + r) * Kp + k0 + ac * 8, 16);                            \
        }                                                                                  \
        CP_COMMIT();                                                                       \
    } while (0)

    DENSE_LOAD(0, 0);
    DENSE_LOAD(1, 1);
    for (int it = 0; it < nch; ++it) {
        int stg = it % 3;
        if (it + 1 < nch) CP_WAIT1(); else CP_WAIT0();
        __syncthreads();
        if (it + 2 < nch) DENSE_LOAD(it + 2, (it + 2) % 3);
        mma_stage(sb + (uint32_t)stg * 32768u, sb + (uint32_t)stg * 32768u + 16384u,
                  warp_m, warp_n, lane, acc);
    }
#undef DENSE_LOAD

    int lr = lane >> 2, lc = (lane & 3) * 2;
#pragma unroll
    for (int mi = 0; mi < 4; ++mi)
#pragma unroll
        for (int ni = 0; ni < 4; ++ni)
#pragma unroll
            for (int e = 0; e < 4; ++e) {
                int m = m0 + warp_m * 64 + mi * 16 + lr + ((e >> 1) ? 8 : 0);
                int n = n0 + warp_n * 32 + ni * 8 + lc + (e & 1);
                float v = acc[mi][ni][e] + bias[n];
                if (C3) {
                    __nv_bfloat16 h = __float2bfloat16(v);
                    __nv_bfloat16 l = __float2bfloat16(v - __bfloat162float(h));
                    size_t base = (size_t)m * 3072;
                    if (patB) { C3[base + n] = h; C3[base + 1024 + n] = h; C3[base + 2048 + n] = l; }
                    else      { C3[base + n] = h; C3[base + 1024 + n] = l; C3[base + 2048 + n] = h; }
                } else {
                    Cf[(size_t)m * 1024 + n] = v;
                }
            }
}

// ===================== attention scores: tensor cores =======================
// per (b,h): sc = 0.125 * q . k^T, K'=192 (3 chunks of 64 = head slice of triple)
__global__ void __launch_bounds__(256) attn_qk(
    const __nv_bfloat16* __restrict__ q3, const __nv_bfloat16* __restrict__ k3,
    float* __restrict__ sc) {
    extern __shared__ __align__(16) char smem[];
    uint32_t sb = smem_u32(smem);
    int tid = threadIdx.x, wid = tid >> 5, lane = tid & 31;
    int warp_m = wid >> 2, warp_n = wid & 3;
    int n0 = blockIdx.x * 128, m0 = blockIdx.y * 128;
    int z = blockIdx.z, b = z >> 4, h = z & 15;
    const __nv_bfloat16* qb = q3 + (size_t)(b * 256 + m0) * 3072 + h * 64;
    const __nv_bfloat16* kb = k3 + (size_t)(b * 256 + n0) * 3072 + h * 64;
    int ar = tid >> 3, ac = tid & 7;

#pragma unroll
    for (int ck = 0; ck < 3; ++ck) {
        uint32_t abase = sb + (uint32_t)ck * 32768u;
        uint32_t bbase = abase + 16384u;
#pragma unroll
        for (int rr = 0; rr < 4; ++rr) {
            int r = ar + rr * 32;
            cp16(abase + SMEM_SWZ128(r * 128 + ac * 16),
                 qb + (size_t)r * 3072 + ck * 1024 + ac * 8, 16);
            cp16(bbase + SMEM_SWZ128(r * 128 + ac * 16),
                 kb + (size_t)r * 3072 + ck * 1024 + ac * 8, 16);
        }
        CP_COMMIT();
    }
    CP_WAIT0();
    __syncthreads();

    float acc[4][4][4] = {};
#pragma unroll
    for (int ck = 0; ck < 3; ++ck)
        mma_stage(sb + (uint32_t)ck * 32768u, sb + (uint32_t)ck * 32768u + 16384u,
                  warp_m, warp_n, lane, acc);

    float* scz = sc + (size_t)z * 65536;
    int lr = lane >> 2, lc = (lane & 3) * 2;
#pragma unroll
    for (int mi = 0; mi < 4; ++mi)
#pragma unroll
        for (int ni = 0; ni < 4; ++ni)
#pragma unroll
            for (int e = 0; e < 4; ++e) {
                int m = m0 + warp_m * 64 + mi * 16 + lr + ((e >> 1) ? 8 : 0);
                int n = n0 + warp_n * 32 + ni * 8 + lc + (e & 1);
                scz[(size_t)m * 256 + n] = acc[mi][ni][e] * 0.125f;
            }
}

// ===================== softmax (len 256) -> attn3 triple ====================
__global__ void __launch_bounds__(256) softmax256(const float* __restrict__ sc,
                                                  __nv_bfloat16* __restrict__ attn3) {
    int r = blockIdx.x, tid = threadIdx.x;
    const float* row = sc + (size_t)r * 256;
    float v = row[tid];
    __shared__ float red[256];
    red[tid] = v;
    __syncthreads();
    for (int st = 128; st > 0; st >>= 1) {
        if (tid < st) red[tid] = fmaxf(red[tid], red[tid + st]);
        __syncthreads();
    }
    float m = red[0];
    __syncthreads();
    float e = expf(v - m);
    red[tid] = e;
    __syncthreads();
    for (int st = 128; st > 0; st >>= 1) {
        if (tid < st) red[tid] += red[tid + st];
        __syncthreads();
    }
    float p = e / red[0];
    __nv_bfloat16 h = __float2bfloat16(p);
    __nv_bfloat16 l = __float2bfloat16(p - __bfloat162float(h));
    size_t ob = (size_t)r * 768;
    attn3[ob + tid] = h;            // pattern A: [hi | lo | hi] over j
    attn3[ob + 256 + tid] = l;
    attn3[ob + 512 + tid] = h;
}

// ===================== v -> vT3 (per head transpose, pattern B over j) ======
__global__ void __launch_bounds__(256) vt3_kernel(const float* __restrict__ v,
                                                  __nv_bfloat16* __restrict__ vt3) {
    __shared__ float tile[128][65];
    int z = blockIdx.x, b = z >> 4, h = z & 15;
    int tid = threadIdx.x;
    for (int jh = 0; jh < 2; ++jh) {
        // coalesced load: consecutive tid -> consecutive d
        for (int it = 0; it < 32; ++it) {
            int idx = it * 256 + tid;
            int d = idx & 63, jj = idx >> 6;
            tile[jj][d] = v[(size_t)(b * 256 + jh * 128 + jj) * 1024 + h * 64 + d];
        }
        __syncthreads();
        // coalesced store: consecutive tid -> consecutive j
        for (int it = 0; it < 32; ++it) {
            int idx = it * 256 + tid;
            int j = idx & 127, d = idx >> 7;
            float x = tile[j][d];
            __nv_bfloat16 hh = __float2bfloat16(x);
            __nv_bfloat16 ll = __float2bfloat16(x - __bfloat162float(hh));
            size_t base = ((size_t)z * 64 + d) * 768 + jh * 128 + j;
            vt3[base] = hh;          // pattern B: [hi | hi | lo] over j
            vt3[base + 256] = hh;
            vt3[base + 512] = ll;
        }
        __syncthreads();
    }
}

// ===================== attn . v : tensor cores ==============================
// per (b,h): ctx[qi, d] = attn3[qi,:768] . vt3[d,:768];  tile 128x64, 4 warps
__global__ void __launch_bounds__(128) attn_av(
    const __nv_bfloat16* __restrict__ attn3, const __nv_bfloat16* __restrict__ vt3,
    float* __restrict__ ctx) {
    extern __shared__ __align__(16) char smem[];
    uint32_t sb = smem_u32(smem);
    int tid = threadIdx.x, wid = tid >> 5, lane = tid & 31;
    int warp_m = wid >> 1, warp_n = wid & 1;
    int m0 = blockIdx.x * 128;
    int z = blockIdx.y, b = z >> 4, h = z & 15;
    const __nv_bfloat16* ab = attn3 + (size_t)(z * 256 + m0) * 768;
    const __nv_bfloat16* bb = vt3 + (size_t)z * 64 * 768;
    int ar = tid >> 3, ac = tid & 7;   // ar 0..15

    float acc[4][4][4] = {};
    const int nch = 12;

#define AV_LOAD(it, stg) do {                                                              \
        int k0 = (it) << 6;                                                                \
        uint32_t abase = sb + (uint32_t)(stg) * 24576u;                                    \
        uint32_t bbase = abase + 16384u;                                                   \
        _Pragma("unroll")                                                                  \
        for (int rr = 0; rr < 8; ++rr) {                                                   \
            int r = ar + rr * 16;                                                          \
            cp16(abase + SMEM_SWZ128(r * 128 + ac * 16),                                   \
                 ab + (size_t)r * 768 + k0 + ac * 8, 16);                                  \
        }                                                                                  \
        _Pragma("unroll")                                                                  \
        for (int rr = 0; rr < 4; ++rr) {                                                   \
            int r = ar + rr * 16;                                                          \
            cp16(bbase + SMEM_SWZ128(r * 128 + ac * 16),                                   \
                 bb + (size_t)r * 768 + k0 + ac * 8, 16);                                  \
        }                                                                                  \
        CP_COMMIT();                                                                       \
    } while (0)

    AV_LOAD(0, 0);
    AV_LOAD(1, 1);
    for (int it = 0; it < nch; ++it) {
        int stg = it % 3;
        if (it + 1 < nch) CP_WAIT1(); else CP_WAIT0();
        __syncthreads();
        if (it + 2 < nch) AV_LOAD(it + 2, (it + 2) % 3);
        mma_stage(sb + (uint32_t)stg * 24576u, sb + (uint32_t)stg * 24576u + 16384u,
                  warp_m, warp_n, lane, acc);
    }
#undef AV_LOAD

    int lr = lane >> 2, lc = (lane & 3) * 2;
#pragma unroll
    for (int mi = 0; mi < 4; ++mi)
#pragma unroll
        for (int ni = 0; ni < 4; ++ni)
#pragma unroll
            for (int e = 0; e < 4; ++e) {
                int qi = m0 + warp_m * 64 + mi * 16 + lr + ((e >> 1) ? 8 : 0);
                int n = warp_n * 32 + ni * 8 + lc + (e & 1);
                ctx[(size_t)(b * 256 + qi) * 1024 + h * 64 + n] = acc[mi][ni][e];
            }
}

// ===================== LN + GELU -> z3 triple ===============================
__global__ void __launch_bounds__(256) ln_gelu_kernel(
    const float* __restrict__ zin, const float* __restrict__ gam,
    const float* __restrict__ bet, __nv_bfloat16* __restrict__ z3) {
    int r = blockIdx.x, tid = threadIdx.x;
    const float* row = zin + (size_t)r * Dm;
    float v[4];
    float s = 0.f, sq = 0.f;
#pragma unroll
    for (int j = 0; j < 4; ++j) {
        v[j] = row[tid + j * 256];
        s += v[j];
        sq += v[j] * v[j];
    }
    __shared__ float rs[256], rq[256];
    rs[tid] = s; rq[tid] = sq;
    __syncthreads();
    for (int st = 128; st > 0; st >>= 1) {
        if (tid < st) { rs[tid] += rs[tid + st]; rq[tid] += rq[tid + st]; }
        __syncthreads();
    }
    float mean = rs[0] * (1.f / 1024.f);
    float var = rq[0] * (1.f / 1024.f) - mean * mean;
    float inv = rsqrtf(var + 1e-5f);
    size_t ob = (size_t)r * 3072;
#pragma unroll
    for (int j = 0; j < 4; ++j) {
        int c = tid + j * 256;
        float y = (v[j] - mean) * inv * gam[c] + bet[c];
        float ge = 0.5f * y * (1.f + erff(y * 0.70710678118654752f));
        __nv_bfloat16 h = __float2bfloat16(ge);
        __nv_bfloat16 l = __float2bfloat16(ge - __bfloat162float(h));
        z3[ob + c] = h; z3[ob + 1024 + c] = l; z3[ob + 2048 + c] = h;
    }
}

// ===================== GAT pieces ===========================================
__global__ void __launch_bounds__(256) e1e2_kernel(
    const float* __restrict__ hg, const float* __restrict__ a1,
    const float* __restrict__ a2, float* __restrict__ e1, float* __restrict__ e2) {
    int n = blockIdx.x, tid = threadIdx.x;
    int h = tid >> 5, lane = tid & 31;
    const float* base = hg + (size_t)n * Dm + h * GD;
    float s1 = 0.f, s2 = 0.f;
#pragma unroll
    for (int j = 0; j < 4; ++j) {
        int d = lane + j * 32;
        float v = base[d];
        s1 += v * a1[d];
        s2 += v * a2[d];
    }
#pragma unroll
    for (int off = 16; off > 0; off >>= 1) {
        s1 += __shfl_down_sync(0xffffffffu, s1, off);
        s2 += __shfl_down_sync(0xffffffffu, s2, off);
    }
    if (lane == 0) { e1[n * HG + h] = s1; e2[n * HG + h] = s2; }
}

__global__ void __launch_bounds__(256) e2max_kernel(const float* __restrict__ e2,
                                                    float* __restrict__ e2m) {
    __shared__ float red[256];
    int h = blockIdx.x, tid = threadIdx.x;
    float m = -3.4e38f;
    for (int n = tid; n < Nn; n += 256) m = fmaxf(m, e2[n * HG + h]);
    red[tid] = m;
    __syncthreads();
    for (int st = 128; st > 0; st >>= 1) {
        if (tid < st) red[tid] = fmaxf(red[tid], red[tid + st]);
        __syncthreads();
    }
    if (tid == 0) e2m[h] = red[0];
}

#define TI 16
__global__ void __launch_bounds__(256) gat_agg_kernel(
    const float* __restrict__ hg, const float* __restrict__ e1,
    const float* __restrict__ e2, const float* __restrict__ e2m,
    const float* __restrict__ feat, float* __restrict__ out) {
    int h = blockIdx.y;
    int i0 = blockIdx.x * TI;
    int tid = threadIdx.x;
    __shared__ float ws[TI][129];
    __shared__ float e2s[128];
    __shared__ float sm_i[TI], ss_i[TI];
    __shared__ float red[TI][17];

    if (tid < TI) {
        float s = e1[(i0 + tid) * HG + h];
        ss_i[tid] = s;
        float vmx = s + e2m[h];
        sm_i[tid] = vmx > 0.f ? vmx : 0.2f * vmx;
    }
    __syncthreads();

    int d = tid & 127;
    int g = tid >> 7;
    int i_base = g * 8;
    int i_w = tid & 15;
    int jgrp = tid >> 4;
    float s_i = ss_i[i_w];
    float m_i = sm_i[i_w];

    float acc[8] = {0.f, 0.f, 0.f, 0.f, 0.f, 0.f, 0.f, 0.f};
    float psum = 0.f;

    for (int jc = 0; jc < Nn / 128; ++jc) {
        if (tid < 128) e2s[tid] = e2[(jc * 128 + tid) * HG + h];
        __syncthreads();
#pragma unroll
        for (int s = 0; s < 8; ++s) {
            int jl = jgrp * 8 + s;
            float vv = s_i + e2s[jl];
            float lr = vv > 0.f ? vv : 0.2f * vv;
            float w = expf(lr - m_i);
            ws[i_w][jl] = w;
            psum += w;
        }
        __syncthreads();
        const float* hgp = hg + (size_t)(jc * 128) * Dm + h * GD + d;
#pragma unroll 4
        for (int jl = 0; jl < 128; ++jl) {
            float hv = hgp[(size_t)jl * Dm];
#pragma unroll
            for (int ii = 0; ii < 8; ++ii) acc[ii] += ws[i_base + ii][jl] * hv;
        }
        __syncthreads();
    }
    red[i_w][jgrp] = psum;
    __syncthreads();
    if (tid < TI) {
        float s = 0.f;
        for (int jg = 0; jg < 16; ++jg) s += red[tid][jg];
        red[tid][16] = s;
    }
    __syncthreads();
#pragma unroll
    for (int ii = 0; ii < 8; ++ii) {
        int i = i0 + i_base + ii;
        float v = acc[ii] / red[i_base + ii][16];
        float o = v > 0.f ? v : expm1f(v);
        size_t idx = (size_t)i * Dm + h * GD + d;
        out[idx] = o + feat[idx];
    }
}

// ===================== host orchestration ===================================
#define TC_SMEM 98304
#define AV_SMEM 73728

extern "C" void kernel_launch(void* const* d_in, const int* in_sizes, int n_in,
                              void* d_out, int out_size) {
    const float* features = (const float*)d_in[0];
    const float* conv_w[5];
    const float* conv_b[5];
    bool interleaved = (in_sizes[2] == 1024);
    for (int i = 0; i < 5; ++i) {
        if (interleaved) {
            conv_w[i] = (const float*)d_in[1 + 2 * i];
            conv_b[i] = (const float*)d_in[2 + 2 * i];
        } else {
            conv_w[i] = (const float*)d_in[1 + i];
            conv_b[i] = (const float*)d_in[6 + i];
        }
    }
    const float* fp_w = (const float*)d_in[11];
    const float* fp_b = (const float*)d_in[12];
    const float* ln_g = (const float*)d_in[13];
    const float* ln_b = (const float*)d_in[14];
    const float* wq = (const float*)d_in[15];
    const float* bq = (const float*)d_in[16];
    const float* wk = (const float*)d_in[17];
    const float* bk = (const float*)d_in[18];
    const float* wv = (const float*)d_in[19];
    const float* bv = (const float*)d_in[20];
    const float* wo = (const float*)d_in[21];
    const float* bo = (const float*)d_in[22];
    const float* gat_w = (const float*)d_in[23];
    const float* gat_b = (const float*)d_in[24];
    const float* ga1 = (const float*)d_in[25];
    const float* ga2 = (const float*)d_in[26];
    float* out = (float*)d_out;

    __nv_bfloat16 *x3, *ms3, *z3, *q3, *k3, *ctx3, *att3, *attn3, *vt3;
    __nv_bfloat16 *wc3, *fpw3, *wq3, *wk3, *wv3, *wo3, *gw3;
    float *zpre, *v, *sc, *ctx, *hg, *e1, *e2, *e2m;
    cudaGetSymbolAddress((void**)&x3, g_x3);
    cudaGetSymbolAddress((void**)&ms3, g_ms3);
    cudaGetSymbolAddress((void**)&z3, g_z3);
    cudaGetSymbolAddress((void**)&q3, g_q3);
    cudaGetSymbolAddress((void**)&k3, g_k3);
    cudaGetSymbolAddress((void**)&ctx3, g_ctx3);
    cudaGetSymbolAddress((void**)&att3, g_att3);
    cudaGetSymbolAddress((void**)&attn3, g_attn3);
    cudaGetSymbolAddress((void**)&vt3, g_vt3);
    cudaGetSymbolAddress((void**)&wc3, g_wc3);
    cudaGetSymbolAddress((void**)&fpw3, g_fpw3);
    cudaGetSymbolAddress((void**)&wq3, g_wq3);
    cudaGetSymbolAddress((void**)&wk3, g_wk3);
    cudaGetSymbolAddress((void**)&wv3, g_wv3);
    cudaGetSymbolAddress((void**)&wo3, g_wo3);
    cudaGetSymbolAddress((void**)&gw3, g_gw3);
    cudaGetSymbolAddress((void**)&zpre, g_zpre);
    cudaGetSymbolAddress((void**)&v, g_v);
    cudaGetSymbolAddress((void**)&sc, g_scores);
    cudaGetSymbolAddress((void**)&ctx, g_ctx);
    cudaGetSymbolAddress((void**)&hg, g_hg);
    cudaGetSymbolAddress((void**)&e1, g_e1);
    cudaGetSymbolAddress((void**)&e2, g_e2);
    cudaGetSymbolAddress((void**)&e2m, g_e2max);

    cudaFuncSetAttribute(conv_tc, cudaFuncAttributeMaxDynamicSharedMemorySize, TC_SMEM);
    cudaFuncSetAttribute(dense_tc, cudaFuncAttributeMaxDynamicSharedMemorySize, TC_SMEM);
    cudaFuncSetAttribute(attn_qk, cudaFuncAttributeMaxDynamicSharedMemorySize, TC_SMEM);
    cudaFuncSetAttribute(attn_av, cudaFuncAttributeMaxDynamicSharedMemorySize, AV_SMEM);

    // 1) splits
    split_mat<<<Nn, 256>>>(features, x3, 1024, 0);
    for (int dd = 0; dd < 5; ++dd)
        split_conv_w<<<1024, 256>>>(conv_w[dd], wc3 + (size_t)dd * 1024 * 21504);
    split_mat<<<1024, 256>>>(fp_w, fpw3, 5120, 1);
    split_mat<<<1024, 256>>>(wq, wq3, 1024, 1);
    split_mat<<<1024, 256>>>(wk, wk3, 1024, 1);
    split_mat<<<1024, 256>>>(wv, wv3, 1024, 1);
    split_mat<<<1024, 256>>>(wo, wo3, 1024, 1);
    split_mat<<<1024, 256>>>(gat_w, gw3, 1024, 1);

    // 2) conv bank -> ms3 triple
    conv_tc<<<dim3(8, 16, 5), 256, TC_SMEM>>>(x3, wc3, conv_b[0], conv_b[1], conv_b[2],
                                              conv_b[3], conv_b[4], ms3);

    // 3) fusion projection -> zpre (fp32)
    dense_tc<<<dim3(8, 16), 256, TC_SMEM>>>(ms3, fpw3, fp_b, zpre, nullptr, 15360, 0);

    // 4) LN + GELU -> z3 triple
    ln_gelu_kernel<<<Nn, 256>>>(zpre, ln_g, ln_b, z3);

    // 5) Q,K,V projections (q3/k3 triple, v fp32)
    dense_tc<<<dim3(8, 16), 256, TC_SMEM>>>(z3, wq3, bq, nullptr, q3, 3072, 0);
    dense_tc<<<dim3(8, 16), 256, TC_SMEM>>>(z3, wk3, bk, nullptr, k3, 3072, 1);
    dense_tc<<<dim3(8, 16), 256, TC_SMEM>>>(z3, wv3, bv, v, nullptr, 3072, 0);

    // 6) attention: scores (TC) -> softmax (emits attn3) -> vT3 -> AV (TC)
    attn_qk<<<dim3(2, 2, 128), 256, TC_SMEM>>>(q3, k3, sc);
    softmax256<<<Bsz * HM * Tn, 256>>>(sc, attn3);
    vt3_kernel<<<128, 256>>>(v, vt3);
    attn_av<<<dim3(2, 128), 128, AV_SMEM>>>(attn3, vt3, ctx);

    // 7) output projection -> att3 triple (feeds GAT GEMM only)
    split_mat<<<Nn, 256>>>(ctx, ctx3, 1024, 0);
    dense_tc<<<dim3(8, 16), 256, TC_SMEM>>>(ctx3, wo3, bo, nullptr, att3, 3072, 0);

    // 8) GAT projection -> hg (fp32)
    dense_tc<<<dim3(8, 16), 256, TC_SMEM>>>(att3, gw3, gat_b, hg, nullptr, 3072, 0);

    // 9) GAT logits + aggregate + residual
    e1e2_kernel<<<Nn, 256>>>(hg, ga1, ga2, e1, e2);
    e2max_kernel<<<HG, 256>>>(e2, e2m);
    gat_agg_kernel<<<dim3(Nn / TI, HG), 256>>>(hg, e1, e2, e2m, features, out);
}

// round 16
// speedup vs baseline: 1.0168x; 1.0168x over previous
#include <cuda_runtime.h>
#include <cuda_bf16.h>
#include <math.h>
#include <stdint.h>

#define Bsz 8
#define Tn 256
#define Dm 1024
#define Nn 2048
#define MS_W 5120
#define HM 16
#define DH 64
#define HG 8
#define GD 128

// ===================== portable PTX helpers (compute_103-safe) ==============
__device__ __forceinline__ uint32_t smem_u32(const void* p) {
    uint32_t a;
    asm("{ .reg .u64 t; cvta.to.shared.u64 t, %1; cvt.u32.u64 %0, t; }" : "=r"(a) : "l"(p));
    return a;
}
#define SMEM_SWZ128(x) ((x) ^ (((x) >> 3) & 0x70))

__device__ __forceinline__ void cp16(uint32_t dst, const void* src, int sz) {
    asm volatile("cp.async.cg.shared.global [%0], [%1], 16, %2;" ::"r"(dst), "l"(src), "r"(sz));
}
#define CP_COMMIT() asm volatile("cp.async.commit_group;" ::: "memory")
#define CP_WAIT1() asm volatile("cp.async.wait_group 1;" ::: "memory")
#define CP_WAIT0() asm volatile("cp.async.wait_group 0;" ::: "memory")

__device__ __forceinline__ void ldsm4(uint32_t& r0, uint32_t& r1, uint32_t& r2, uint32_t& r3,
                                      uint32_t a) {
    asm volatile("ldmatrix.sync.aligned.m8n8.x4.shared.b16 {%0,%1,%2,%3}, [%4];"
                 : "=r"(r0), "=r"(r1), "=r"(r2), "=r"(r3) : "r"(a));
}
__device__ __forceinline__ void mma16816(float* d, const uint32_t* a, const uint32_t* b) {
    asm volatile(
        "mma.sync.aligned.m16n8k16.row.col.f32.bf16.bf16.f32 "
        "{%0,%1,%2,%3}, {%4,%5,%6,%7}, {%8,%9}, {%0,%1,%2,%3};"
        : "+f"(d[0]), "+f"(d[1]), "+f"(d[2]), "+f"(d[3])
        : "r"(a[0]), "r"(a[1]), "r"(a[2]), "r"(a[3]), "r"(b[0]), "r"(b[1]));
}

// ===================== scratch =============================================
__device__ __align__(16) __nv_bfloat16 g_x3[(size_t)Nn * 3072];
__device__ __align__(16) __nv_bfloat16 g_ms3[(size_t)Nn * 15360];
__device__ __align__(16) __nv_bfloat16 g_z3[(size_t)Nn * 3072];
__device__ __align__(16) __nv_bfloat16 g_q3[(size_t)Nn * 3072];
__device__ __align__(16) __nv_bfloat16 g_k3[(size_t)Nn * 3072];
__device__ __align__(16) __nv_bfloat16 g_ctx3[(size_t)Nn * 3072];
__device__ __align__(16) __nv_bfloat16 g_att3[(size_t)Nn * 3072];
__device__ __align__(16) __nv_bfloat16 g_attn3[(size_t)Bsz * HM * Tn * 768];
__device__ __align__(16) __nv_bfloat16 g_vt3[(size_t)Bsz * HM * DH * 768];
__device__ __align__(16) __nv_bfloat16 g_wc3[(size_t)5 * 1024 * 21504];
__device__ __align__(16) __nv_bfloat16 g_fpw3[(size_t)1024 * 15360];
__device__ __align__(16) __nv_bfloat16 g_wq3[(size_t)1024 * 3072];
__device__ __align__(16) __nv_bfloat16 g_wk3[(size_t)1024 * 3072];
__device__ __align__(16) __nv_bfloat16 g_wv3[(size_t)1024 * 3072];
__device__ __align__(16) __nv_bfloat16 g_wo3[(size_t)1024 * 3072];
__device__ __align__(16) __nv_bfloat16 g_gw3[(size_t)1024 * 3072];

__device__ float g_zpre[(size_t)Nn * Dm];
__device__ float g_v[(size_t)Nn * Dm];
__device__ float g_scores[(size_t)Bsz * HM * Tn * Tn];
__device__ float g_ctx[(size_t)Nn * Dm];
__device__ float g_hg[(size_t)Nn * Dm];
__device__ float g_e1[Nn * HG];
__device__ float g_e2[Nn * HG];
__device__ float g_e2max[HG];

__constant__ int c_dils[5] = {1, 2, 4, 8, 16};

// ===================== split conversions ====================================
__global__ void __launch_bounds__(256) split_mat(const float* __restrict__ in,
                                                 __nv_bfloat16* __restrict__ out,
                                                 int Cd, int patB) {
    int r = blockIdx.x;
    size_t ib = (size_t)r * Cd, ob = (size_t)r * 3 * Cd;
    for (int c = threadIdx.x; c < Cd; c += 256) {
        float x = in[ib + c];
        __nv_bfloat16 h = __float2bfloat16(x);
        __nv_bfloat16 l = __float2bfloat16(x - __bfloat162float(h));
        if (patB) { out[ob + c] = h; out[ob + Cd + c] = h; out[ob + 2 * Cd + c] = l; }
        else      { out[ob + c] = h; out[ob + Cd + c] = l; out[ob + 2 * Cd + c] = h; }
    }
}

// conv weight w[o][i][k] -> wc3[o][kk*3072 + {i:hi, 1024+i:hi, 2048+i:lo}]
// coalesced: stage the 7168-float row through smem first.
__global__ void __launch_bounds__(256) split_conv_w(const float* __restrict__ w,
                                                    __nv_bfloat16* __restrict__ out) {
    __shared__ float buf[7168];
    int o = blockIdx.x;
    const float* wr = w + (size_t)o * 7168;
    for (int idx = threadIdx.x; idx < 7168; idx += 256) buf[idx] = wr[idx];
    __syncthreads();
    for (int i = threadIdx.x; i < 1024; i += 256) {
#pragma unroll
        for (int kk = 0; kk < 7; ++kk) {
            float x = buf[i * 7 + kk];
            __nv_bfloat16 h = __float2bfloat16(x);
            __nv_bfloat16 l = __float2bfloat16(x - __bfloat162float(h));
            size_t base = (size_t)o * 21504 + kk * 3072;
            out[base + i] = h; out[base + 1024 + i] = h; out[base + 2048 + i] = l;
        }
    }
}

// ===================== warp-MMA compute core ================================
__device__ __forceinline__ void mma_stage(uint32_t sA, uint32_t sB, int warp_m, int warp_n,
                                          int lane, float acc[4][4][4]) {
    int lrow = lane & 15;
    int lcol = (lane >> 4) * 16;
#pragma unroll
    for (int ks = 0; ks < 4; ++ks) {
        uint32_t a[4][4];
        uint32_t b[4][2];
#pragma unroll
        for (int mi = 0; mi < 4; ++mi) {
            int row = warp_m * 64 + mi * 16 + lrow;
            uint32_t addr = sA + SMEM_SWZ128(row * 128 + ks * 32 + lcol);
            ldsm4(a[mi][0], a[mi][1], a[mi][2], a[mi][3], addr);
        }
#pragma unroll
        for (int nj = 0; nj < 2; ++nj) {
            int row = warp_n * 32 + nj * 16 + lrow;
            uint32_t addr = sB + SMEM_SWZ128(row * 128 + ks * 32 + lcol);
            uint32_t r0, r1, r2, r3;
            ldsm4(r0, r1, r2, r3, addr);
            b[nj * 2][0] = r0;     b[nj * 2][1] = r2;
            b[nj * 2 + 1][0] = r1; b[nj * 2 + 1][1] = r3;
        }
#pragma unroll
        for (int mi = 0; mi < 4; ++mi)
#pragma unroll
            for (int ni = 0; ni < 4; ++ni)
                mma16816(acc[mi][ni], a[mi], b[ni]);
    }
}

// ===================== conv GEMM (implicit shift, K'=21504) =================
// 2-stage 64KB pipeline (3 CTAs/SM) — measured fastest configuration.
__global__ void __launch_bounds__(256) conv_tc(
    const __nv_bfloat16* __restrict__ x3, const __nv_bfloat16* __restrict__ wc3,
    const float* __restrict__ b0, const float* __restrict__ b1,
    const float* __restrict__ b2, const float* __restrict__ b3,
    const float* __restrict__ b4, __nv_bfloat16* __restrict__ ms3) {
    extern __shared__ __align__(16) char smem[];
    uint32_t sb = smem_u32(smem);
    int tid = threadIdx.x, wid = tid >> 5, lane = tid & 31;
    int warp_m = wid >> 2, warp_n = wid & 3;
    int n0 = blockIdx.x * 128, m0 = blockIdx.y * 128;
    int dz = blockIdx.z, dil = c_dils[dz];
    const __nv_bfloat16* B3 = wc3 + (size_t)dz * 1024 * 21504;
    int seqbase = m0 & ~255, trow0 = m0 & 255;
    int ar = tid >> 3, ac = tid & 7;

    float acc[4][4][4] = {};
    const int nch = 21504 / 64;   // 336

#define CONV_LOAD(it, stg) do {                                                            \
        int k0 = (it) << 6;                                                                \
        int kk = k0 / 3072;                                                                \
        int inner0 = k0 - kk * 3072;                                                       \
        int shift = (kk - 3) * dil;                                                        \
        uint32_t abase = sb + (uint32_t)(stg) * 32768u;                                    \
        uint32_t bbase = abase + 16384u;                                                   \
        _Pragma("unroll")                                                                  \
        for (int rr = 0; rr < 4; ++rr) {                                                   \
            int r = ar + rr * 32;                                                          \
            int t = trow0 + r + shift;                                                     \
            int ok = ((unsigned)t < 256u) ? 16 : 0;                                        \
            int tc2 = ok ? t : 0;                                                          \
            cp16(abase + SMEM_SWZ128(r * 128 + ac * 16),                                   \
                 x3 + (size_t)(seqbase + tc2) * 3072 + inner0 + ac * 8, ok);               \
            cp16(bbase + SMEM_SWZ128(r * 128 + ac * 16),                                   \
                 B3 + (size_t)(n0 + r) * 21504 + k0 + ac * 8, 16);                         \
        }                                                                                  \
        CP_COMMIT();                                                                       \
    } while (0)

    CONV_LOAD(0, 0);
    for (int it = 0; it < nch; ++it) {
        int stg = it & 1;
        if (it + 1 < nch) { CONV_LOAD(it + 1, 1 - stg); CP_WAIT1(); }
        else CP_WAIT0();
        __syncthreads();
        mma_stage(sb + (uint32_t)stg * 32768u, sb + (uint32_t)stg * 32768u + 16384u,
                  warp_m, warp_n, lane, acc);
        __syncthreads();
    }
#undef CONV_LOAD

    const float* bias = dz == 0 ? b0 : dz == 1 ? b1 : dz == 2 ? b2 : dz == 3 ? b3 : b4;
    int lr = lane >> 2, lc = (lane & 3) * 2;
#pragma unroll
    for (int mi = 0; mi < 4; ++mi)
#pragma unroll
        for (int ni = 0; ni < 4; ++ni)
#pragma unroll
            for (int e = 0; e < 4; ++e) {
                int m = m0 + warp_m * 64 + mi * 16 + lr + ((e >> 1) ? 8 : 0);
                int n = n0 + warp_n * 32 + ni * 8 + lc + (e & 1);
                float v = acc[mi][ni][e] + bias[n];
                __nv_bfloat16 h = __float2bfloat16(v);
                __nv_bfloat16 l = __float2bfloat16(v - __bfloat162float(h));
                size_t rbase = (size_t)m * 15360;
                size_t col = (size_t)dz * 1024 + n;
                ms3[rbase + col] = h;
                ms3[rbase + 5120 + col] = l;
                ms3[rbase + 10240 + col] = h;
            }
}

// ===================== dense GEMM: C = A3 . B3^T + bias =====================
__global__ void __launch_bounds__(256) dense_tc(
    const __nv_bfloat16* __restrict__ A3, const __nv_bfloat16* __restrict__ B3,
    const float* __restrict__ bias, float* __restrict__ Cf,
    __nv_bfloat16* __restrict__ C3, int Kp, int patB) {
    extern __shared__ __align__(16) char smem[];
    uint32_t sb = smem_u32(smem);
    int tid = threadIdx.x, wid = tid >> 5, lane = tid & 31;
    int warp_m = wid >> 2, warp_n = wid & 3;
    int n0 = blockIdx.x * 128, m0 = blockIdx.y * 128;
    int ar = tid >> 3, ac = tid & 7;

    float acc[4][4][4] = {};
    int nch = Kp >> 6;

#define DENSE_LOAD(it, stg) do {                                                           \
        int k0 = (it) << 6;                                                                \
        uint32_t abase = sb + (uint32_t)(stg) * 32768u;                                    \
        uint32_t bbase = abase + 16384u;                                                   \
        _Pragma("unroll")                                                                  \
        for (int rr = 0; rr < 4; ++rr) {                                                   \
            int r = ar + rr * 32;                                                          \
            cp16(abase + SMEM_SWZ128(r * 128 + ac * 16),                                   \
                 A3 + (size_t)(m0 + r) * Kp + k0 + ac * 8, 16);                            \
            cp16(bbase + SMEM_SWZ128(r * 128 + ac * 16),                                   \
                 B3 + (size_t)(n0 + r) * Kp + k0 + ac * 8, 16);                            \
        }                                                                                  \
        CP_COMMIT();                                                                       \
    } while (0)

    DENSE_LOAD(0, 0);
    for (int it = 0; it < nch; ++it) {
        int stg = it & 1;
        if (it + 1 < nch) { DENSE_LOAD(it + 1, 1 - stg); CP_WAIT1(); }
        else CP_WAIT0();
        __syncthreads();
        mma_stage(sb + (uint32_t)stg * 32768u, sb + (uint32_t)stg * 32768u + 16384u,
                  warp_m, warp_n, lane, acc);
        __syncthreads();
    }
#undef DENSE_LOAD

    int lr = lane >> 2, lc = (lane & 3) * 2;
#pragma unroll
    for (int mi = 0; mi < 4; ++mi)
#pragma unroll
        for (int ni = 0; ni < 4; ++ni)
#pragma unroll
            for (int e = 0; e < 4; ++e) {
                int m = m0 + warp_m * 64 + mi * 16 + lr + ((e >> 1) ? 8 : 0);
                int n = n0 + warp_n * 32 + ni * 8 + lc + (e & 1);
                float v = acc[mi][ni][e] + bias[n];
                if (C3) {
                    __nv_bfloat16 h = __float2bfloat16(v);
                    __nv_bfloat16 l = __float2bfloat16(v - __bfloat162float(h));
                    size_t base = (size_t)m * 3072;
                    if (patB) { C3[base + n] = h; C3[base + 1024 + n] = h; C3[base + 2048 + n] = l; }
                    else      { C3[base + n] = h; C3[base + 1024 + n] = l; C3[base + 2048 + n] = h; }
                } else {
                    Cf[(size_t)m * 1024 + n] = v;
                }
            }
}

// ===================== attention scores: tensor cores (2-stage, 64KB) =======
__global__ void __launch_bounds__(256) attn_qk(
    const __nv_bfloat16* __restrict__ q3, const __nv_bfloat16* __restrict__ k3,
    float* __restrict__ sc) {
    extern __shared__ __align__(16) char smem[];
    uint32_t sb = smem_u32(smem);
    int tid = threadIdx.x, wid = tid >> 5, lane = tid & 31;
    int warp_m = wid >> 2, warp_n = wid & 3;
    int n0 = blockIdx.x * 128, m0 = blockIdx.y * 128;
    int z = blockIdx.z, b = z >> 4, h = z & 15;
    const __nv_bfloat16* qb = q3 + (size_t)(b * 256 + m0) * 3072 + h * 64;
    const __nv_bfloat16* kb = k3 + (size_t)(b * 256 + n0) * 3072 + h * 64;
    int ar = tid >> 3, ac = tid & 7;

    float acc[4][4][4] = {};
    const int nch = 3;

#define QK_LOAD(it, stg) do {                                                              \
        uint32_t abase = sb + (uint32_t)(stg) * 32768u;                                    \
        uint32_t bbase = abase + 16384u;                                                   \
        _Pragma("unroll")                                                                  \
        for (int rr = 0; rr < 4; ++rr) {                                                   \
            int r = ar + rr * 32;                                                          \
            cp16(abase + SMEM_SWZ128(r * 128 + ac * 16),                                   \
                 qb + (size_t)r * 3072 + (it) * 1024 + ac * 8, 16);                        \
            cp16(bbase + SMEM_SWZ128(r * 128 + ac * 16),                                   \
                 kb + (size_t)r * 3072 + (it) * 1024 + ac * 8, 16);                        \
        }                                                                                  \
        CP_COMMIT();                                                                       \
    } while (0)

    QK_LOAD(0, 0);
    for (int it = 0; it < nch; ++it) {
        int stg = it & 1;
        if (it + 1 < nch) { QK_LOAD(it + 1, 1 - stg); CP_WAIT1(); }
        else CP_WAIT0();
        __syncthreads();
        mma_stage(sb + (uint32_t)stg * 32768u, sb + (uint32_t)stg * 32768u + 16384u,
                  warp_m, warp_n, lane, acc);
        __syncthreads();
    }
#undef QK_LOAD

    float* scz = sc + (size_t)z * 65536;
    int lr = lane >> 2, lc = (lane & 3) * 2;
#pragma unroll
    for (int mi = 0; mi < 4; ++mi)
#pragma unroll
        for (int ni = 0; ni < 4; ++ni)
#pragma unroll
            for (int e = 0; e < 4; ++e) {
                int m = m0 + warp_m * 64 + mi * 16 + lr + ((e >> 1) ? 8 : 0);
                int n = n0 + warp_n * 32 + ni * 8 + lc + (e & 1);
                scz[(size_t)m * 256 + n] = acc[mi][ni][e] * 0.125f;
            }
}

// ===================== softmax (len 256) -> attn3 triple ====================
__global__ void __launch_bounds__(256) softmax256(const float* __restrict__ sc,
                                                  __nv_bfloat16* __restrict__ attn3) {
    int r = blockIdx.x, tid = threadIdx.x;
    const float* row = sc + (size_t)r * 256;
    float v = row[tid];
    __shared__ float red[256];
    red[tid] = v;
    __syncthreads();
    for (int st = 128; st > 0; st >>= 1) {
        if (tid < st) red[tid] = fmaxf(red[tid], red[tid + st]);
        __syncthreads();
    }
    float m = red[0];
    __syncthreads();
    float e = expf(v - m);
    red[tid] = e;
    __syncthreads();
    for (int st = 128; st > 0; st >>= 1) {
        if (tid < st) red[tid] += red[tid + st];
        __syncthreads();
    }
    float p = e / red[0];
    __nv_bfloat16 h = __float2bfloat16(p);
    __nv_bfloat16 l = __float2bfloat16(p - __bfloat162float(h));
    size_t ob = (size_t)r * 768;
    attn3[ob + tid] = h;
    attn3[ob + 256 + tid] = l;
    attn3[ob + 512 + tid] = h;
}

// ===================== v -> vT3 (per head transpose, pattern B over j) ======
__global__ void __launch_bounds__(256) vt3_kernel(const float* __restrict__ v,
                                                  __nv_bfloat16* __restrict__ vt3) {
    __shared__ float tile[128][65];
    int z = blockIdx.x, b = z >> 4, h = z & 15;
    int tid = threadIdx.x;
    for (int jh = 0; jh < 2; ++jh) {
        for (int it = 0; it < 32; ++it) {
            int idx = it * 256 + tid;
            int d = idx & 63, jj = idx >> 6;
            tile[jj][d] = v[(size_t)(b * 256 + jh * 128 + jj) * 1024 + h * 64 + d];
        }
        __syncthreads();
        for (int it = 0; it < 32; ++it) {
            int idx = it * 256 + tid;
            int j = idx & 127, d = idx >> 7;
            float x = tile[j][d];
            __nv_bfloat16 hh = __float2bfloat16(x);
            __nv_bfloat16 ll = __float2bfloat16(x - __bfloat162float(hh));
            size_t base = ((size_t)z * 64 + d) * 768 + jh * 128 + j;
            vt3[base] = hh;
            vt3[base + 256] = hh;
            vt3[base + 512] = ll;
        }
        __syncthreads();
    }
}

// ===================== attn . v : tensor cores (2-stage, 48KB) ==============
__global__ void __launch_bounds__(128) attn_av(
    const __nv_bfloat16* __restrict__ attn3, const __nv_bfloat16* __restrict__ vt3,
    float* __restrict__ ctx) {
    extern __shared__ __align__(16) char smem[];
    uint32_t sb = smem_u32(smem);
    int tid = threadIdx.x, wid = tid >> 5, lane = tid & 31;
    int warp_m = wid >> 1, warp_n = wid & 1;
    int m0 = blockIdx.x * 128;
    int z = blockIdx.y, b = z >> 4, h = z & 15;
    const __nv_bfloat16* ab = attn3 + (size_t)(z * 256 + m0) * 768;
    const __nv_bfloat16* bb = vt3 + (size_t)z * 64 * 768;
    int ar = tid >> 3, ac = tid & 7;

    float acc[4][4][4] = {};
    const int nch = 12;

#define AV_LOAD(it, stg) do {                                                              \
        int k0 = (it) << 6;                                                                \
        uint32_t abase = sb + (uint32_t)(stg) * 24576u;                                    \
        uint32_t bbase = abase + 16384u;                                                   \
        _Pragma("unroll")                                                                  \
        for (int rr = 0; rr < 8; ++rr) {                                                   \
            int r = ar + rr * 16;                                                          \
            cp16(abase + SMEM_SWZ128(r * 128 + ac * 16),                                   \
                 ab + (size_t)r * 768 + k0 + ac * 8, 16);                                  \
        }                                                                                  \
        _Pragma("unroll")                                                                  \
        for (int rr = 0; rr < 4; ++rr) {                                                   \
            int r = ar + rr * 16;                                                          \
            cp16(bbase + SMEM_SWZ128(r * 128 + ac * 16),                                   \
                 bb + (size_t)r * 768 + k0 + ac * 8, 16);                                  \
        }                                                                                  \
        CP_COMMIT();                                                                       \
    } while (0)

    AV_LOAD(0, 0);
    for (int it = 0; it < nch; ++it) {
        int stg = it & 1;
        if (it + 1 < nch) { AV_LOAD(it + 1, 1 - stg); CP_WAIT1(); }
        else CP_WAIT0();
        __syncthreads();
        mma_stage(sb + (uint32_t)stg * 24576u, sb + (uint32_t)stg * 24576u + 16384u,
                  warp_m, warp_n, lane, acc);
        __syncthreads();
    }
#undef AV_LOAD

    int lr = lane >> 2, lc = (lane & 3) * 2;
#pragma unroll
    for (int mi = 0; mi < 4; ++mi)
#pragma unroll
        for (int ni = 0; ni < 4; ++ni)
#pragma unroll
            for (int e = 0; e < 4; ++e) {
                int qi = m0 + warp_m * 64 + mi * 16 + lr + ((e >> 1) ? 8 : 0);
                int n = warp_n * 32 + ni * 8 + lc + (e & 1);
                ctx[(size_t)(b * 256 + qi) * 1024 + h * 64 + n] = acc[mi][ni][e];
            }
}

// ===================== LN + GELU -> z3 triple ===============================
__global__ void __launch_bounds__(256) ln_gelu_kernel(
    const float* __restrict__ zin, const float* __restrict__ gam,
    const float* __restrict__ bet, __nv_bfloat16* __restrict__ z3) {
    int r = blockIdx.x, tid = threadIdx.x;
    const float* row = zin + (size_t)r * Dm;
    float v[4];
    float s = 0.f, sq = 0.f;
#pragma unroll
    for (int j = 0; j < 4; ++j) {
        v[j] = row[tid + j * 256];
        s += v[j];
        sq += v[j] * v[j];
    }
    __shared__ float rs[256], rq[256];
    rs[tid] = s; rq[tid] = sq;
    __syncthreads();
    for (int st = 128; st > 0; st >>= 1) {
        if (tid < st) { rs[tid] += rs[tid + st]; rq[tid] += rq[tid + st]; }
        __syncthreads();
    }
    float mean = rs[0] * (1.f / 1024.f);
    float var = rq[0] * (1.f / 1024.f) - mean * mean;
    float inv = rsqrtf(var + 1e-5f);
    size_t ob = (size_t)r * 3072;
#pragma unroll
    for (int j = 0; j < 4; ++j) {
        int c = tid + j * 256;
        float y = (v[j] - mean) * inv * gam[c] + bet[c];
        float ge = 0.5f * y * (1.f + erff(y * 0.70710678118654752f));
        __nv_bfloat16 h = __float2bfloat16(ge);
        __nv_bfloat16 l = __float2bfloat16(ge - __bfloat162float(h));
        z3[ob + c] = h; z3[ob + 1024 + c] = l; z3[ob + 2048 + c] = h;
    }
}

// ===================== GAT pieces ===========================================
__global__ void __launch_bounds__(256) e1e2_kernel(
    const float* __restrict__ hg, const float* __restrict__ a1,
    const float* __restrict__ a2, float* __restrict__ e1, float* __restrict__ e2) {
    int n = blockIdx.x, tid = threadIdx.x;
    int h = tid >> 5, lane = tid & 31;
    const float* base = hg + (size_t)n * Dm + h * GD;
    float s1 = 0.f, s2 = 0.f;
#pragma unroll
    for (int j = 0; j < 4; ++j) {
        int d = lane + j * 32;
        float v = base[d];
        s1 += v * a1[d];
        s2 += v * a2[d];
    }
#pragma unroll
    for (int off = 16; off > 0; off >>= 1) {
        s1 += __shfl_down_sync(0xffffffffu, s1, off);
        s2 += __shfl_down_sync(0xffffffffu, s2, off);
    }
    if (lane == 0) { e1[n * HG + h] = s1; e2[n * HG + h] = s2; }
}

__global__ void __launch_bounds__(256) e2max_kernel(const float* __restrict__ e2,
                                                    float* __restrict__ e2m) {
    __shared__ float red[256];
    int h = blockIdx.x, tid = threadIdx.x;
    float m = -3.4e38f;
    for (int n = tid; n < Nn; n += 256) m = fmaxf(m, e2[n * HG + h]);
    red[tid] = m;
    __syncthreads();
    for (int st = 128; st > 0; st >>= 1) {
        if (tid < st) red[tid] = fmaxf(red[tid], red[tid + st]);
        __syncthreads();
    }
    if (tid == 0) e2m[h] = red[0];
}

#define TI 16
__global__ void __launch_bounds__(256) gat_agg_kernel(
    const float* __restrict__ hg, const float* __restrict__ e1,
    const float* __restrict__ e2, const float* __restrict__ e2m,
    const float* __restrict__ feat, float* __restrict__ out) {
    int h = blockIdx.y;
    int i0 = blockIdx.x * TI;
    int tid = threadIdx.x;
    __shared__ float ws[TI][129];
    __shared__ float e2s[128];
    __shared__ float sm_i[TI], ss_i[TI];
    __shared__ float red[TI][17];

    if (tid < TI) {
        float s = e1[(i0 + tid) * HG + h];
        ss_i[tid] = s;
        float vmx = s + e2m[h];
        sm_i[tid] = vmx > 0.f ? vmx : 0.2f * vmx;
    }
    __syncthreads();

    int d = tid & 127;
    int g = tid >> 7;
    int i_base = g * 8;
    int i_w = tid & 15;
    int jgrp = tid >> 4;
    float s_i = ss_i[i_w];
    float m_i = sm_i[i_w];

    float acc[8] = {0.f, 0.f, 0.f, 0.f, 0.f, 0.f, 0.f, 0.f};
    float psum = 0.f;

    for (int jc = 0; jc < Nn / 128; ++jc) {
        if (tid < 128) e2s[tid] = e2[(jc * 128 + tid) * HG + h];
        __syncthreads();
#pragma unroll
        for (int s = 0; s < 8; ++s) {
            int jl = jgrp * 8 + s;
            float vv = s_i + e2s[jl];
            float lr = vv > 0.f ? vv : 0.2f * vv;
            float w = expf(lr - m_i);
            ws[i_w][jl] = w;
            psum += w;
        }
        __syncthreads();
        const float* hgp = hg + (size_t)(jc * 128) * Dm + h * GD + d;
#pragma unroll 4
        for (int jl = 0; jl < 128; ++jl) {
            float hv = hgp[(size_t)jl * Dm];
#pragma unroll
            for (int ii = 0; ii < 8; ++ii) acc[ii] += ws[i_base + ii][jl] * hv;
        }
        __syncthreads();
    }
    red[i_w][jgrp] = psum;
    __syncthreads();
    if (tid < TI) {
        float s = 0.f;
        for (int jg = 0; jg < 16; ++jg) s += red[tid][jg];
        red[tid][16] = s;
    }
    __syncthreads();
#pragma unroll
    for (int ii = 0; ii < 8; ++ii) {
        int i = i0 + i_base + ii;
        float v = acc[ii] / red[i_base + ii][16];
        float o = v > 0.f ? v : expm1f(v);
        size_t idx = (size_t)i * Dm + h * GD + d;
        out[idx] = o + feat[idx];
    }
}

// ===================== host orchestration ===================================
#define TC_SMEM 65536
#define AV_SMEM 49152

extern "C" void kernel_launch(void* const* d_in, const int* in_sizes, int n_in,
                              void* d_out, int out_size) {
    const float* features = (const float*)d_in[0];
    const float* conv_w[5];
    const float* conv_b[5];
    bool interleaved = (in_sizes[2] == 1024);
    for (int i = 0; i < 5; ++i) {
        if (interleaved) {
            conv_w[i] = (const float*)d_in[1 + 2 * i];
            conv_b[i] = (const float*)d_in[2 + 2 * i];
        } else {
            conv_w[i] = (const float*)d_in[1 + i];
            conv_b[i] = (const float*)d_in[6 + i];
        }
    }
    const float* fp_w = (const float*)d_in[11];
    const float* fp_b = (const float*)d_in[12];
    const float* ln_g = (const float*)d_in[13];
    const float* ln_b = (const float*)d_in[14];
    const float* wq = (const float*)d_in[15];
    const float* bq = (const float*)d_in[16];
    const float* wk = (const float*)d_in[17];
    const float* bk = (const float*)d_in[18];
    const float* wv = (const float*)d_in[19];
    const float* bv = (const float*)d_in[20];
    const float* wo = (const float*)d_in[21];
    const float* bo = (const float*)d_in[22];
    const float* gat_w = (const float*)d_in[23];
    const float* gat_b = (const float*)d_in[24];
    const float* ga1 = (const float*)d_in[25];
    const float* ga2 = (const float*)d_in[26];
    float* out = (float*)d_out;

    __nv_bfloat16 *x3, *ms3, *z3, *q3, *k3, *ctx3, *att3, *attn3, *vt3;
    __nv_bfloat16 *wc3, *fpw3, *wq3, *wk3, *wv3, *wo3, *gw3;
    float *zpre, *v, *sc, *ctx, *hg, *e1, *e2, *e2m;
    cudaGetSymbolAddress((void**)&x3, g_x3);
    cudaGetSymbolAddress((void**)&ms3, g_ms3);
    cudaGetSymbolAddress((void**)&z3, g_z3);
    cudaGetSymbolAddress((void**)&q3, g_q3);
    cudaGetSymbolAddress((void**)&k3, g_k3);
    cudaGetSymbolAddress((void**)&ctx3, g_ctx3);
    cudaGetSymbolAddress((void**)&att3, g_att3);
    cudaGetSymbolAddress((void**)&attn3, g_attn3);
    cudaGetSymbolAddress((void**)&vt3, g_vt3);
    cudaGetSymbolAddress((void**)&wc3, g_wc3);
    cudaGetSymbolAddress((void**)&fpw3, g_fpw3);
    cudaGetSymbolAddress((void**)&wq3, g_wq3);
    cudaGetSymbolAddress((void**)&wk3, g_wk3);
    cudaGetSymbolAddress((void**)&wv3, g_wv3);
    cudaGetSymbolAddress((void**)&wo3, g_wo3);
    cudaGetSymbolAddress((void**)&gw3, g_gw3);
    cudaGetSymbolAddress((void**)&zpre, g_zpre);
    cudaGetSymbolAddress((void**)&v, g_v);
    cudaGetSymbolAddress((void**)&sc, g_scores);
    cudaGetSymbolAddress((void**)&ctx, g_ctx);
    cudaGetSymbolAddress((void**)&hg, g_hg);
    cudaGetSymbolAddress((void**)&e1, g_e1);
    cudaGetSymbolAddress((void**)&e2, g_e2);
    cudaGetSymbolAddress((void**)&e2m, g_e2max);

    cudaFuncSetAttribute(conv_tc, cudaFuncAttributeMaxDynamicSharedMemorySize, TC_SMEM);
    cudaFuncSetAttribute(dense_tc, cudaFuncAttributeMaxDynamicSharedMemorySize, TC_SMEM);
    cudaFuncSetAttribute(attn_qk, cudaFuncAttributeMaxDynamicSharedMemorySize, TC_SMEM);
    cudaFuncSetAttribute(attn_av, cudaFuncAttributeMaxDynamicSharedMemorySize, AV_SMEM);

    // 1) splits
    split_mat<<<Nn, 256>>>(features, x3, 1024, 0);
    for (int dd = 0; dd < 5; ++dd)
        split_conv_w<<<1024, 256>>>(conv_w[dd], wc3 + (size_t)dd * 1024 * 21504);
    split_mat<<<1024, 256>>>(fp_w, fpw3, 5120, 1);
    split_mat<<<1024, 256>>>(wq, wq3, 1024, 1);
    split_mat<<<1024, 256>>>(wk, wk3, 1024, 1);
    split_mat<<<1024, 256>>>(wv, wv3, 1024, 1);
    split_mat<<<1024, 256>>>(wo, wo3, 1024, 1);
    split_mat<<<1024, 256>>>(gat_w, gw3, 1024, 1);

    // 2) conv bank -> ms3 triple
    conv_tc<<<dim3(8, 16, 5), 256, TC_SMEM>>>(x3, wc3, conv_b[0], conv_b[1], conv_b[2],
                                              conv_b[3], conv_b[4], ms3);

    // 3) fusion projection -> zpre (fp32)
    dense_tc<<<dim3(8, 16), 256, TC_SMEM>>>(ms3, fpw3, fp_b, zpre, nullptr, 15360, 0);

    // 4) LN + GELU -> z3 triple
    ln_gelu_kernel<<<Nn, 256>>>(zpre, ln_g, ln_b, z3);

    // 5) Q,K,V projections (q3/k3 triple, v fp32)
    dense_tc<<<dim3(8, 16), 256, TC_SMEM>>>(z3, wq3, bq, nullptr, q3, 3072, 0);
    dense_tc<<<dim3(8, 16), 256, TC_SMEM>>>(z3, wk3, bk, nullptr, k3, 3072, 1);
    dense_tc<<<dim3(8, 16), 256, TC_SMEM>>>(z3, wv3, bv, v, nullptr, 3072, 0);

    // 6) attention: scores (TC) -> softmax (emits attn3) -> vT3 -> AV (TC)
    attn_qk<<<dim3(2, 2, 128), 256, TC_SMEM>>>(q3, k3, sc);
    softmax256<<<Bsz * HM * Tn, 256>>>(sc, attn3);
    vt3_kernel<<<128, 256>>>(v, vt3);
    attn_av<<<dim3(2, 128), 128, AV_SMEM>>>(attn3, vt3, ctx);

    // 7) output projection -> att3 triple (feeds GAT GEMM only)
    split_mat<<<Nn, 256>>>(ctx, ctx3, 1024, 0);
    dense_tc<<<dim3(8, 16), 256, TC_SMEM>>>(ctx3, wo3, bo, nullptr, att3, 3072, 0);

    // 8) GAT projection -> hg (fp32)
    dense_tc<<<dim3(8, 16), 256, TC_SMEM>>>(att3, gw3, gat_b, hg, nullptr, 3072, 0);

    // 9) GAT logits + aggregate + residual
    e1e2_kernel<<<Nn, 256>>>(hg, ga1, ga2, e1, e2);
    e2max_kernel<<<HG, 256>>>(e2, e2m);
    gat_agg_kernel<<<dim3(Nn / TI, HG), 256>>>(hg, e1, e2, e2m, features, out);
}

// round 17
// speedup vs baseline: 1.2356x; 1.2152x over previous
#include <cuda_runtime.h>
#include <cuda_bf16.h>
#include <cuda_fp16.h>
#include <math.h>
#include <stdint.h>

#define Bsz 8
#define Tn 256
#define Dm 1024
#define Nn 2048
#define MS_W 5120
#define HM 16
#define DH 64
#define HG 8
#define GD 128

// ===================== portable PTX helpers (compute_103-safe) ==============
__device__ __forceinline__ uint32_t smem_u32(const void* p) {
    uint32_t a;
    asm("{ .reg .u64 t; cvta.to.shared.u64 t, %1; cvt.u32.u64 %0, t; }" : "=r"(a) : "l"(p));
    return a;
}
#define SMEM_SWZ128(x) ((x) ^ (((x) >> 3) & 0x70))

__device__ __forceinline__ void cp16(uint32_t dst, const void* src, int sz) {
    asm volatile("cp.async.cg.shared.global [%0], [%1], 16, %2;" ::"r"(dst), "l"(src), "r"(sz));
}
#define CP_COMMIT() asm volatile("cp.async.commit_group;" ::: "memory")
#define CP_WAIT1() asm volatile("cp.async.wait_group 1;" ::: "memory")
#define CP_WAIT0() asm volatile("cp.async.wait_group 0;" ::: "memory")

__device__ __forceinline__ void ldsm4(uint32_t& r0, uint32_t& r1, uint32_t& r2, uint32_t& r3,
                                      uint32_t a) {
    asm volatile("ldmatrix.sync.aligned.m8n8.x4.shared.b16 {%0,%1,%2,%3}, [%4];"
                 : "=r"(r0), "=r"(r1), "=r"(r2), "=r"(r3) : "r"(a));
}
__device__ __forceinline__ void mma16816(float* d, const uint32_t* a, const uint32_t* b) {
    asm volatile(
        "mma.sync.aligned.m16n8k16.row.col.f32.bf16.bf16.f32 "
        "{%0,%1,%2,%3}, {%4,%5,%6,%7}, {%8,%9}, {%0,%1,%2,%3};"
        : "+f"(d[0]), "+f"(d[1]), "+f"(d[2]), "+f"(d[3])
        : "r"(a[0]), "r"(a[1]), "r"(a[2]), "r"(a[3]), "r"(b[0]), "r"(b[1]));
}
__device__ __forceinline__ void mma16816h(float* d, const uint32_t* a, const uint32_t* b) {
    asm volatile(
        "mma.sync.aligned.m16n8k16.row.col.f32.f16.f16.f32 "
        "{%0,%1,%2,%3}, {%4,%5,%6,%7}, {%8,%9}, {%0,%1,%2,%3};"
        : "+f"(d[0]), "+f"(d[1]), "+f"(d[2]), "+f"(d[3])
        : "r"(a[0]), "r"(a[1]), "r"(a[2]), "r"(a[3]), "r"(b[0]), "r"(b[1]));
}

// ===================== scratch =============================================
// fp16 2-term conv operands
__device__ __align__(16) __half g_x2[(size_t)Nn * 2048];                 // [h | 64*l]
__device__ __align__(16) __half g_wc2[(size_t)5 * 1024 * 14336];         // per kk: [h | h/64]
// bf16 3-term (everything else)
__device__ __align__(16) __nv_bfloat16 g_ms3[(size_t)Nn * 15360];
__device__ __align__(16) __nv_bfloat16 g_z3[(size_t)Nn * 3072];
__device__ __align__(16) __nv_bfloat16 g_q3[(size_t)Nn * 3072];
__device__ __align__(16) __nv_bfloat16 g_k3[(size_t)Nn * 3072];
__device__ __align__(16) __nv_bfloat16 g_ctx3[(size_t)Nn * 3072];
__device__ __align__(16) __nv_bfloat16 g_att3[(size_t)Nn * 3072];
__device__ __align__(16) __nv_bfloat16 g_attn3[(size_t)Bsz * HM * Tn * 768];
__device__ __align__(16) __nv_bfloat16 g_vt3[(size_t)Bsz * HM * DH * 768];
__device__ __align__(16) __nv_bfloat16 g_fpw3[(size_t)1024 * 15360];
__device__ __align__(16) __nv_bfloat16 g_wq3[(size_t)1024 * 3072];
__device__ __align__(16) __nv_bfloat16 g_wk3[(size_t)1024 * 3072];
__device__ __align__(16) __nv_bfloat16 g_wv3[(size_t)1024 * 3072];
__device__ __align__(16) __nv_bfloat16 g_wo3[(size_t)1024 * 3072];
__device__ __align__(16) __nv_bfloat16 g_gw3[(size_t)1024 * 3072];

__device__ float g_zpre[(size_t)Nn * Dm];
__device__ float g_v[(size_t)Nn * Dm];
__device__ float g_scores[(size_t)Bsz * HM * Tn * Tn];
__device__ float g_ctx[(size_t)Nn * Dm];
__device__ float g_hg[(size_t)Nn * Dm];
__device__ float g_e1[Nn * HG];
__device__ float g_e2[Nn * HG];
__device__ float g_e2max[HG];

__constant__ int c_dils[5] = {1, 2, 4, 8, 16};

// ===================== split conversions ====================================
__global__ void __launch_bounds__(256) split_mat(const float* __restrict__ in,
                                                 __nv_bfloat16* __restrict__ out,
                                                 int Cd, int patB) {
    int r = blockIdx.x;
    size_t ib = (size_t)r * Cd, ob = (size_t)r * 3 * Cd;
    for (int c = threadIdx.x; c < Cd; c += 256) {
        float x = in[ib + c];
        __nv_bfloat16 h = __float2bfloat16(x);
        __nv_bfloat16 l = __float2bfloat16(x - __bfloat162float(h));
        if (patB) { out[ob + c] = h; out[ob + Cd + c] = h; out[ob + 2 * Cd + c] = l; }
        else      { out[ob + c] = h; out[ob + Cd + c] = l; out[ob + 2 * Cd + c] = h; }
    }
}

// features -> x2 fp16: [h(x) | 64*l(x)]
__global__ void __launch_bounds__(256) split_x2(const float* __restrict__ in,
                                                __half* __restrict__ out) {
    int r = blockIdx.x;
    size_t ib = (size_t)r * 1024, ob = (size_t)r * 2048;
    for (int c = threadIdx.x; c < 1024; c += 256) {
        float x = in[ib + c];
        __half h = __float2half(x);
        float l = x - __half2float(h);
        out[ob + c] = h;
        out[ob + 1024 + c] = __float2half(l * 64.f);
    }
}

// all 5 conv weights -> wc2 fp16: per kk 2048 cols = [h(w) | h(w)/64]
__global__ void __launch_bounds__(256) split_conv_w2(
    const float* __restrict__ w0, const float* __restrict__ w1,
    const float* __restrict__ w2, const float* __restrict__ w3,
    const float* __restrict__ w4, __half* __restrict__ out) {
    __shared__ float buf[7168];
    int dz = blockIdx.y, o = blockIdx.x;
    const float* w = dz == 0 ? w0 : dz == 1 ? w1 : dz == 2 ? w2 : dz == 3 ? w3 : w4;
    const float* wr = w + (size_t)o * 7168;
    for (int idx = threadIdx.x; idx < 7168; idx += 256) buf[idx] = wr[idx];
    __syncthreads();
    size_t obase = (size_t)dz * 1024 * 14336 + (size_t)o * 14336;
    for (int i = threadIdx.x; i < 1024; i += 256) {
#pragma unroll
        for (int kk = 0; kk < 7; ++kk) {
            float x = buf[i * 7 + kk];
            __half h = __float2half(x);
            size_t base = obase + kk * 2048;
            out[base + i] = h;
            out[base + 1024 + i] = __float2half(__half2float(h) * (1.f / 64.f));
        }
    }
}

// ===================== warp-MMA compute cores ===============================
__device__ __forceinline__ void mma_stage(uint32_t sA, uint32_t sB, int warp_m, int warp_n,
                                          int lane, float acc[4][4][4]) {
    int lrow = lane & 15;
    int lcol = (lane >> 4) * 16;
#pragma unroll
    for (int ks = 0; ks < 4; ++ks) {
        uint32_t a[4][4];
        uint32_t b[4][2];
#pragma unroll
        for (int mi = 0; mi < 4; ++mi) {
            int row = warp_m * 64 + mi * 16 + lrow;
            uint32_t addr = sA + SMEM_SWZ128(row * 128 + ks * 32 + lcol);
            ldsm4(a[mi][0], a[mi][1], a[mi][2], a[mi][3], addr);
        }
#pragma unroll
        for (int nj = 0; nj < 2; ++nj) {
            int row = warp_n * 32 + nj * 16 + lrow;
            uint32_t addr = sB + SMEM_SWZ128(row * 128 + ks * 32 + lcol);
            uint32_t r0, r1, r2, r3;
            ldsm4(r0, r1, r2, r3, addr);
            b[nj * 2][0] = r0;     b[nj * 2][1] = r2;
            b[nj * 2 + 1][0] = r1; b[nj * 2 + 1][1] = r3;
        }
#pragma unroll
        for (int mi = 0; mi < 4; ++mi)
#pragma unroll
            for (int ni = 0; ni < 4; ++ni)
                mma16816(acc[mi][ni], a[mi], b[ni]);
    }
}

__device__ __forceinline__ void mma_stage_h(uint32_t sA, uint32_t sB, int warp_m, int warp_n,
                                            int lane, float acc[4][4][4]) {
    int lrow = lane & 15;
    int lcol = (lane >> 4) * 16;
#pragma unroll
    for (int ks = 0; ks < 4; ++ks) {
        uint32_t a[4][4];
        uint32_t b[4][2];
#pragma unroll
        for (int mi = 0; mi < 4; ++mi) {
            int row = warp_m * 64 + mi * 16 + lrow;
            uint32_t addr = sA + SMEM_SWZ128(row * 128 + ks * 32 + lcol);
            ldsm4(a[mi][0], a[mi][1], a[mi][2], a[mi][3], addr);
        }
#pragma unroll
        for (int nj = 0; nj < 2; ++nj) {
            int row = warp_n * 32 + nj * 16 + lrow;
            uint32_t addr = sB + SMEM_SWZ128(row * 128 + ks * 32 + lcol);
            uint32_t r0, r1, r2, r3;
            ldsm4(r0, r1, r2, r3, addr);
            b[nj * 2][0] = r0;     b[nj * 2][1] = r2;
            b[nj * 2 + 1][0] = r1; b[nj * 2 + 1][1] = r3;
        }
#pragma unroll
        for (int mi = 0; mi < 4; ++mi)
#pragma unroll
            for (int ni = 0; ni < 4; ++ni)
                mma16816h(acc[mi][ni], a[mi], b[ni]);
    }
}

// ===================== conv GEMM (fp16 2-term, K'=14336) ====================
__global__ void __launch_bounds__(256) conv_tc(
    const __half* __restrict__ x2, const __half* __restrict__ wc2,
    const float* __restrict__ b0, const float* __restrict__ b1,
    const float* __restrict__ b2, const float* __restrict__ b3,
    const float* __restrict__ b4, __nv_bfloat16* __restrict__ ms3) {
    extern __shared__ __align__(16) char smem[];
    uint32_t sb = smem_u32(smem);
    int tid = threadIdx.x, wid = tid >> 5, lane = tid & 31;
    int warp_m = wid >> 2, warp_n = wid & 3;
    int n0 = blockIdx.x * 128, m0 = blockIdx.y * 128;
    int dz = blockIdx.z, dil = c_dils[dz];
    const __half* B3 = wc2 + (size_t)dz * 1024 * 14336;
    int seqbase = m0 & ~255, trow0 = m0 & 255;
    int ar = tid >> 3, ac = tid & 7;

    float acc[4][4][4] = {};
    const int nch = 14336 / 64;   // 224

#define CONV_LOAD(it, stg) do {                                                            \
        int k0 = (it) << 6;                                                                \
        int kk = k0 >> 11;                                                                 \
        int inner0 = k0 & 2047;                                                            \
        int shift = (kk - 3) * dil;                                                        \
        uint32_t abase = sb + (uint32_t)(stg) * 32768u;                                    \
        uint32_t bbase = abase + 16384u;                                                   \
        _Pragma("unroll")                                                                  \
        for (int rr = 0; rr < 4; ++rr) {                                                   \
            int r = ar + rr * 32;                                                          \
            int t = trow0 + r + shift;                                                     \
            int ok = ((unsigned)t < 256u) ? 16 : 0;                                        \
            int tc2 = ok ? t : 0;                                                          \
            cp16(abase + SMEM_SWZ128(r * 128 + ac * 16),                                   \
                 x2 + (size_t)(seqbase + tc2) * 2048 + inner0 + ac * 8, ok);               \
            cp16(bbase + SMEM_SWZ128(r * 128 + ac * 16),                                   \
                 B3 + (size_t)(n0 + r) * 14336 + k0 + ac * 8, 16);                         \
        }                                                                                  \
        CP_COMMIT();                                                                       \
    } while (0)

    CONV_LOAD(0, 0);
    for (int it = 0; it < nch; ++it) {
        int stg = it & 1;
        if (it + 1 < nch) { CONV_LOAD(it + 1, 1 - stg); CP_WAIT1(); }
        else CP_WAIT0();
        __syncthreads();
        mma_stage_h(sb + (uint32_t)stg * 32768u, sb + (uint32_t)stg * 32768u + 16384u,
                    warp_m, warp_n, lane, acc);
        __syncthreads();
    }
#undef CONV_LOAD

    const float* bias = dz == 0 ? b0 : dz == 1 ? b1 : dz == 2 ? b2 : dz == 3 ? b3 : b4;
    int lr = lane >> 2, lc = (lane & 3) * 2;
#pragma unroll
    for (int mi = 0; mi < 4; ++mi)
#pragma unroll
        for (int ni = 0; ni < 4; ++ni)
#pragma unroll
            for (int e = 0; e < 4; ++e) {
                int m = m0 + warp_m * 64 + mi * 16 + lr + ((e >> 1) ? 8 : 0);
                int n = n0 + warp_n * 32 + ni * 8 + lc + (e & 1);
                float v = acc[mi][ni][e] + bias[n];
                __nv_bfloat16 h = __float2bfloat16(v);
                __nv_bfloat16 l = __float2bfloat16(v - __bfloat162float(h));
                size_t rbase = (size_t)m * 15360;
                size_t col = (size_t)dz * 1024 + n;
                ms3[rbase + col] = h;
                ms3[rbase + 5120 + col] = l;
                ms3[rbase + 10240 + col] = h;
            }
}

// ===================== dense GEMM: C = A3 . B3^T + bias (bf16 3-term) =======
__global__ void __launch_bounds__(256) dense_tc(
    const __nv_bfloat16* __restrict__ A3, const __nv_bfloat16* __restrict__ B3,
    const float* __restrict__ bias, float* __restrict__ Cf,
    __nv_bfloat16* __restrict__ C3, int Kp, int patB) {
    extern __shared__ __align__(16) char smem[];
    uint32_t sb = smem_u32(smem);
    int tid = threadIdx.x, wid = tid >> 5, lane = tid & 31;
    int warp_m = wid >> 2, warp_n = wid & 3;
    int n0 = blockIdx.x * 128, m0 = blockIdx.y * 128;
    int ar = tid >> 3, ac = tid & 7;

    float acc[4][4][4] = {};
    int nch = Kp >> 6;

#define DENSE_LOAD(it, stg) do {                                                           \
        int k0 = (it) << 6;                                                                \
        uint32_t abase = sb + (uint32_t)(stg) * 32768u;                                    \
        uint32_t bbase = abase + 16384u;                                                   \
        _Pragma("unroll")                                                                  \
        for (int rr = 0; rr < 4; ++rr) {                                                   \
            int r = ar + rr * 32;                                                          \
            cp16(abase + SMEM_SWZ128(r * 128 + ac * 16),                                   \
                 A3 + (size_t)(m0 + r) * Kp + k0 + ac * 8, 16);                            \
            cp16(bbase + SMEM_SWZ128(r * 128 + ac * 16),                                   \
                 B3 + (size_t)(n0 + r) * Kp + k0 + ac * 8, 16);                            \
        }                                                                                  \
        CP_COMMIT();                                                                       \
    } while (0)

    DENSE_LOAD(0, 0);
    for (int it = 0; it < nch; ++it) {
        int stg = it & 1;
        if (it + 1 < nch) { DENSE_LOAD(it + 1, 1 - stg); CP_WAIT1(); }
        else CP_WAIT0();
        __syncthreads();
        mma_stage(sb + (uint32_t)stg * 32768u, sb + (uint32_t)stg * 32768u + 16384u,
                  warp_m, warp_n, lane, acc);
        __syncthreads();
    }
#undef DENSE_LOAD

    int lr = lane >> 2, lc = (lane & 3) * 2;
#pragma unroll
    for (int mi = 0; mi < 4; ++mi)
#pragma unroll
        for (int ni = 0; ni < 4; ++ni)
#pragma unroll
            for (int e = 0; e < 4; ++e) {
                int m = m0 + warp_m * 64 + mi * 16 + lr + ((e >> 1) ? 8 : 0);
                int n = n0 + warp_n * 32 + ni * 8 + lc + (e & 1);
                float v = acc[mi][ni][e] + bias[n];
                if (C3) {
                    __nv_bfloat16 h = __float2bfloat16(v);
                    __nv_bfloat16 l = __float2bfloat16(v - __bfloat162float(h));
                    size_t base = (size_t)m * 3072;
                    if (patB) { C3[base + n] = h; C3[base + 1024 + n] = h; C3[base + 2048 + n] = l; }
                    else      { C3[base + n] = h; C3[base + 1024 + n] = l; C3[base + 2048 + n] = h; }
                } else {
                    Cf[(size_t)m * 1024 + n] = v;
                }
            }
}

// ===================== attention scores: tensor cores =======================
__global__ void __launch_bounds__(256) attn_qk(
    const __nv_bfloat16* __restrict__ q3, const __nv_bfloat16* __restrict__ k3,
    float* __restrict__ sc) {
    extern __shared__ __align__(16) char smem[];
    uint32_t sb = smem_u32(smem);
    int tid = threadIdx.x, wid = tid >> 5, lane = tid & 31;
    int warp_m = wid >> 2, warp_n = wid & 3;
    int n0 = blockIdx.x * 128, m0 = blockIdx.y * 128;
    int z = blockIdx.z, b = z >> 4, h = z & 15;
    const __nv_bfloat16* qb = q3 + (size_t)(b * 256 + m0) * 3072 + h * 64;
    const __nv_bfloat16* kb = k3 + (size_t)(b * 256 + n0) * 3072 + h * 64;
    int ar = tid >> 3, ac = tid & 7;

    float acc[4][4][4] = {};
    const int nch = 3;

#define QK_LOAD(it, stg) do {                                                              \
        uint32_t abase = sb + (uint32_t)(stg) * 32768u;                                    \
        uint32_t bbase = abase + 16384u;                                                   \
        _Pragma("unroll")                                                                  \
        for (int rr = 0; rr < 4; ++rr) {                                                   \
            int r = ar + rr * 32;                                                          \
            cp16(abase + SMEM_SWZ128(r * 128 + ac * 16),                                   \
                 qb + (size_t)r * 3072 + (it) * 1024 + ac * 8, 16);                        \
            cp16(bbase + SMEM_SWZ128(r * 128 + ac * 16),                                   \
                 kb + (size_t)r * 3072 + (it) * 1024 + ac * 8, 16);                        \
        }                                                                                  \
        CP_COMMIT();                                                                       \
    } while (0)

    QK_LOAD(0, 0);
    for (int it = 0; it < nch; ++it) {
        int stg = it & 1;
        if (it + 1 < nch) { QK_LOAD(it + 1, 1 - stg); CP_WAIT1(); }
        else CP_WAIT0();
        __syncthreads();
        mma_stage(sb + (uint32_t)stg * 32768u, sb + (uint32_t)stg * 32768u + 16384u,
                  warp_m, warp_n, lane, acc);
        __syncthreads();
    }
#undef QK_LOAD

    float* scz = sc + (size_t)z * 65536;
    int lr = lane >> 2, lc = (lane & 3) * 2;
#pragma unroll
    for (int mi = 0; mi < 4; ++mi)
#pragma unroll
        for (int ni = 0; ni < 4; ++ni)
#pragma unroll
            for (int e = 0; e < 4; ++e) {
                int m = m0 + warp_m * 64 + mi * 16 + lr + ((e >> 1) ? 8 : 0);
                int n = n0 + warp_n * 32 + ni * 8 + lc + (e & 1);
                scz[(size_t)m * 256 + n] = acc[mi][ni][e] * 0.125f;
            }
}

// ===================== softmax (len 256) -> attn3 triple ====================
__global__ void __launch_bounds__(256) softmax256(const float* __restrict__ sc,
                                                  __nv_bfloat16* __restrict__ attn3) {
    int r = blockIdx.x, tid = threadIdx.x;
    const float* row = sc + (size_t)r * 256;
    float v = row[tid];
    __shared__ float red[256];
    red[tid] = v;
    __syncthreads();
    for (int st = 128; st > 0; st >>= 1) {
        if (tid < st) red[tid] = fmaxf(red[tid], red[tid + st]);
        __syncthreads();
    }
    float m = red[0];
    __syncthreads();
    float e = expf(v - m);
    red[tid] = e;
    __syncthreads();
    for (int st = 128; st > 0; st >>= 1) {
        if (tid < st) red[tid] += red[tid + st];
        __syncthreads();
    }
    float p = e / red[0];
    __nv_bfloat16 h = __float2bfloat16(p);
    __nv_bfloat16 l = __float2bfloat16(p - __bfloat162float(h));
    size_t ob = (size_t)r * 768;
    attn3[ob + tid] = h;
    attn3[ob + 256 + tid] = l;
    attn3[ob + 512 + tid] = h;
}

// ===================== v -> vT3 (per head transpose, pattern B over j) ======
__global__ void __launch_bounds__(256) vt3_kernel(const float* __restrict__ v,
                                                  __nv_bfloat16* __restrict__ vt3) {
    __shared__ float tile[128][65];
    int z = blockIdx.x, b = z >> 4, h = z & 15;
    int tid = threadIdx.x;
    for (int jh = 0; jh < 2; ++jh) {
        for (int it = 0; it < 32; ++it) {
            int idx = it * 256 + tid;
            int d = idx & 63, jj = idx >> 6;
            tile[jj][d] = v[(size_t)(b * 256 + jh * 128 + jj) * 1024 + h * 64 + d];
        }
        __syncthreads();
        for (int it = 0; it < 32; ++it) {
            int idx = it * 256 + tid;
            int j = idx & 127, d = idx >> 7;
            float x = tile[j][d];
            __nv_bfloat16 hh = __float2bfloat16(x);
            __nv_bfloat16 ll = __float2bfloat16(x - __bfloat162float(hh));
            size_t base = ((size_t)z * 64 + d) * 768 + jh * 128 + j;
            vt3[base] = hh;
            vt3[base + 256] = hh;
            vt3[base + 512] = ll;
        }
        __syncthreads();
    }
}

// ===================== attn . v : tensor cores ==============================
__global__ void __launch_bounds__(128) attn_av(
    const __nv_bfloat16* __restrict__ attn3, const __nv_bfloat16* __restrict__ vt3,
    float* __restrict__ ctx) {
    extern __shared__ __align__(16) char smem[];
    uint32_t sb = smem_u32(smem);
    int tid = threadIdx.x, wid = tid >> 5, lane = tid & 31;
    int warp_m = wid >> 1, warp_n = wid & 1;
    int m0 = blockIdx.x * 128;
    int z = blockIdx.y, b = z >> 4, h = z & 15;
    const __nv_bfloat16* ab = attn3 + (size_t)(z * 256 + m0) * 768;
    const __nv_bfloat16* bb = vt3 + (size_t)z * 64 * 768;
    int ar = tid >> 3, ac = tid & 7;

    float acc[4][4][4] = {};
    const int nch = 12;

#define AV_LOAD(it, stg) do {                                                              \
        int k0 = (it) << 6;                                                                \
        uint32_t abase = sb + (uint32_t)(stg) * 24576u;                                    \
        uint32_t bbase = abase + 16384u;                                                   \
        _Pragma("unroll")                                                                  \
        for (int rr = 0; rr < 8; ++rr) {                                                   \
            int r = ar + rr * 16;                                                          \
            cp16(abase + SMEM_SWZ128(r * 128 + ac * 16),                                   \
                 ab + (size_t)r * 768 + k0 + ac * 8, 16);                                  \
        }                                                                                  \
        _Pragma("unroll")                                                                  \
        for (int rr = 0; rr < 4; ++rr) {                                                   \
            int r = ar + rr * 16;                                                          \
            cp16(bbase + SMEM_SWZ128(r * 128 + ac * 16),                                   \
                 bb + (size_t)r * 768 + k0 + ac * 8, 16);                                  \
        }                                                                                  \
        CP_COMMIT();                                                                       \
    } while (0)

    AV_LOAD(0, 0);
    for (int it = 0; it < nch; ++it) {
        int stg = it & 1;
        if (it + 1 < nch) { AV_LOAD(it + 1, 1 - stg); CP_WAIT1(); }
        else CP_WAIT0();
        __syncthreads();
        mma_stage(sb + (uint32_t)stg * 24576u, sb + (uint32_t)stg * 24576u + 16384u,
                  warp_m, warp_n, lane, acc);
        __syncthreads();
    }
#undef AV_LOAD

    int lr = lane >> 2, lc = (lane & 3) * 2;
#pragma unroll
    for (int mi = 0; mi < 4; ++mi)
#pragma unroll
        for (int ni = 0; ni < 4; ++ni)
#pragma unroll
            for (int e = 0; e < 4; ++e) {
                int qi = m0 + warp_m * 64 + mi * 16 + lr + ((e >> 1) ? 8 : 0);
                int n = warp_n * 32 + ni * 8 + lc + (e & 1);
                ctx[(size_t)(b * 256 + qi) * 1024 + h * 64 + n] = acc[mi][ni][e];
            }
}

// ===================== LN + GELU -> z3 triple ===============================
__global__ void __launch_bounds__(256) ln_gelu_kernel(
    const float* __restrict__ zin, const float* __restrict__ gam,
    const float* __restrict__ bet, __nv_bfloat16* __restrict__ z3) {
    int r = blockIdx.x, tid = threadIdx.x;
    const float* row = zin + (size_t)r * Dm;
    float v[4];
    float s = 0.f, sq = 0.f;
#pragma unroll
    for (int j = 0; j < 4; ++j) {
        v[j] = row[tid + j * 256];
        s += v[j];
        sq += v[j] * v[j];
    }
    __shared__ float rs[256], rq[256];
    rs[tid] = s; rq[tid] = sq;
    __syncthreads();
    for (int st = 128; st > 0; st >>= 1) {
        if (tid < st) { rs[tid] += rs[tid + st]; rq[tid] += rq[tid + st]; }
        __syncthreads();
    }
    float mean = rs[0] * (1.f / 1024.f);
    float var = rq[0] * (1.f / 1024.f) - mean * mean;
    float inv = rsqrtf(var + 1e-5f);
    size_t ob = (size_t)r * 3072;
#pragma unroll
    for (int j = 0; j < 4; ++j) {
        int c = tid + j * 256;
        float y = (v[j] - mean) * inv * gam[c] + bet[c];
        float ge = 0.5f * y * (1.f + erff(y * 0.70710678118654752f));
        __nv_bfloat16 h = __float2bfloat16(ge);
        __nv_bfloat16 l = __float2bfloat16(ge - __bfloat162float(h));
        z3[ob + c] = h; z3[ob + 1024 + c] = l; z3[ob + 2048 + c] = h;
    }
}

// ===================== GAT pieces ===========================================
__global__ void __launch_bounds__(256) e1e2_kernel(
    const float* __restrict__ hg, const float* __restrict__ a1,
    const float* __restrict__ a2, float* __restrict__ e1, float* __restrict__ e2) {
    int n = blockIdx.x, tid = threadIdx.x;
    int h = tid >> 5, lane = tid & 31;
    const float* base = hg + (size_t)n * Dm + h * GD;
    float s1 = 0.f, s2 = 0.f;
#pragma unroll
    for (int j = 0; j < 4; ++j) {
        int d = lane + j * 32;
        float v = base[d];
        s1 += v * a1[d];
        s2 += v * a2[d];
    }
#pragma unroll
    for (int off = 16; off > 0; off >>= 1) {
        s1 += __shfl_down_sync(0xffffffffu, s1, off);
        s2 += __shfl_down_sync(0xffffffffu, s2, off);
    }
    if (lane == 0) { e1[n * HG + h] = s1; e2[n * HG + h] = s2; }
}

__global__ void __launch_bounds__(256) e2max_kernel(const float* __restrict__ e2,
                                                    float* __restrict__ e2m) {
    __shared__ float red[256];
    int h = blockIdx.x, tid = threadIdx.x;
    float m = -3.4e38f;
    for (int n = tid; n < Nn; n += 256) m = fmaxf(m, e2[n * HG + h]);
    red[tid] = m;
    __syncthreads();
    for (int st = 128; st > 0; st >>= 1) {
        if (tid < st) red[tid] = fmaxf(red[tid], red[tid + st]);
        __syncthreads();
    }
    if (tid == 0) e2m[h] = red[0];
}

#define TI 16
__global__ void __launch_bounds__(256) gat_agg_kernel(
    const float* __restrict__ hg, const float* __restrict__ e1,
    const float* __restrict__ e2, const float* __restrict__ e2m,
    const float* __restrict__ feat, float* __restrict__ out) {
    int h = blockIdx.y;
    int i0 = blockIdx.x * TI;
    int tid = threadIdx.x;
    __shared__ float ws[TI][129];
    __shared__ float e2s[128];
    __shared__ float sm_i[TI], ss_i[TI];
    __shared__ float red[TI][17];

    if (tid < TI) {
        float s = e1[(i0 + tid) * HG + h];
        ss_i[tid] = s;
        float vmx = s + e2m[h];
        sm_i[tid] = vmx > 0.f ? vmx : 0.2f * vmx;
    }
    __syncthreads();

    int d = tid & 127;
    int g = tid >> 7;
    int i_base = g * 8;
    int i_w = tid & 15;
    int jgrp = tid >> 4;
    float s_i = ss_i[i_w];
    float m_i = sm_i[i_w];

    float acc[8] = {0.f, 0.f, 0.f, 0.f, 0.f, 0.f, 0.f, 0.f};
    float psum = 0.f;

    for (int jc = 0; jc < Nn / 128; ++jc) {
        if (tid < 128) e2s[tid] = e2[(jc * 128 + tid) * HG + h];
        __syncthreads();
#pragma unroll
        for (int s = 0; s < 8; ++s) {
            int jl = jgrp * 8 + s;
            float vv = s_i + e2s[jl];
            float lr = vv > 0.f ? vv : 0.2f * vv;
            float w = expf(lr - m_i);
            ws[i_w][jl] = w;
            psum += w;
        }
        __syncthreads();
        const float* hgp = hg + (size_t)(jc * 128) * Dm + h * GD + d;
#pragma unroll 4
        for (int jl = 0; jl < 128; ++jl) {
            float hv = hgp[(size_t)jl * Dm];
#pragma unroll
            for (int ii = 0; ii < 8; ++ii) acc[ii] += ws[i_base + ii][jl] * hv;
        }
        __syncthreads();
    }
    red[i_w][jgrp] = psum;
    __syncthreads();
    if (tid < TI) {
        float s = 0.f;
        for (int jg = 0; jg < 16; ++jg) s += red[tid][jg];
        red[tid][16] = s;
    }
    __syncthreads();
#pragma unroll
    for (int ii = 0; ii < 8; ++ii) {
        int i = i0 + i_base + ii;
        float v = acc[ii] / red[i_base + ii][16];
        float o = v > 0.f ? v : expm1f(v);
        size_t idx = (size_t)i * Dm + h * GD + d;
        out[idx] = o + feat[idx];
    }
}

// ===================== host orchestration ===================================
#define TC_SMEM 65536
#define AV_SMEM 49152

extern "C" void kernel_launch(void* const* d_in, const int* in_sizes, int n_in,
                              void* d_out, int out_size) {
    const float* features = (const float*)d_in[0];
    const float* conv_w[5];
    const float* conv_b[5];
    bool interleaved = (in_sizes[2] == 1024);
    for (int i = 0; i < 5; ++i) {
        if (interleaved) {
            conv_w[i] = (const float*)d_in[1 + 2 * i];
            conv_b[i] = (const float*)d_in[2 + 2 * i];
        } else {
            conv_w[i] = (const float*)d_in[1 + i];
            conv_b[i] = (const float*)d_in[6 + i];
        }
    }
    const float* fp_w = (const float*)d_in[11];
    const float* fp_b = (const float*)d_in[12];
    const float* ln_g = (const float*)d_in[13];
    const float* ln_b = (const float*)d_in[14];
    const float* wq = (const float*)d_in[15];
    const float* bq = (const float*)d_in[16];
    const float* wk = (const float*)d_in[17];
    const float* bk = (const float*)d_in[18];
    const float* wv = (const float*)d_in[19];
    const float* bv = (const float*)d_in[20];
    const float* wo = (const float*)d_in[21];
    const float* bo = (const float*)d_in[22];
    const float* gat_w = (const float*)d_in[23];
    const float* gat_b = (const float*)d_in[24];
    const float* ga1 = (const float*)d_in[25];
    const float* ga2 = (const float*)d_in[26];
    float* out = (float*)d_out;

    __half *x2, *wc2;
    __nv_bfloat16 *ms3, *z3, *q3, *k3, *ctx3, *att3, *attn3, *vt3;
    __nv_bfloat16 *fpw3, *wq3, *wk3, *wv3, *wo3, *gw3;
    float *zpre, *v, *sc, *ctx, *hg, *e1, *e2, *e2m;
    cudaGetSymbolAddress((void**)&x2, g_x2);
    cudaGetSymbolAddress((void**)&wc2, g_wc2);
    cudaGetSymbolAddress((void**)&ms3, g_ms3);
    cudaGetSymbolAddress((void**)&z3, g_z3);
    cudaGetSymbolAddress((void**)&q3, g_q3);
    cudaGetSymbolAddress((void**)&k3, g_k3);
    cudaGetSymbolAddress((void**)&ctx3, g_ctx3);
    cudaGetSymbolAddress((void**)&att3, g_att3);
    cudaGetSymbolAddress((void**)&attn3, g_attn3);
    cudaGetSymbolAddress((void**)&vt3, g_vt3);
    cudaGetSymbolAddress((void**)&fpw3, g_fpw3);
    cudaGetSymbolAddress((void**)&wq3, g_wq3);
    cudaGetSymbolAddress((void**)&wk3, g_wk3);
    cudaGetSymbolAddress((void**)&wv3, g_wv3);
    cudaGetSymbolAddress((void**)&wo3, g_wo3);
    cudaGetSymbolAddress((void**)&gw3, g_gw3);
    cudaGetSymbolAddress((void**)&zpre, g_zpre);
    cudaGetSymbolAddress((void**)&v, g_v);
    cudaGetSymbolAddress((void**)&sc, g_scores);
    cudaGetSymbolAddress((void**)&ctx, g_ctx);
    cudaGetSymbolAddress((void**)&hg, g_hg);
    cudaGetSymbolAddress((void**)&e1, g_e1);
    cudaGetSymbolAddress((void**)&e2, g_e2);
    cudaGetSymbolAddress((void**)&e2m, g_e2max);

    cudaFuncSetAttribute(conv_tc, cudaFuncAttributeMaxDynamicSharedMemorySize, TC_SMEM);
    cudaFuncSetAttribute(dense_tc, cudaFuncAttributeMaxDynamicSharedMemorySize, TC_SMEM);
    cudaFuncSetAttribute(attn_qk, cudaFuncAttributeMaxDynamicSharedMemorySize, TC_SMEM);
    cudaFuncSetAttribute(attn_av, cudaFuncAttributeMaxDynamicSharedMemorySize, AV_SMEM);

    // launch order arranged so conv_tc is launch index 5 (ncu -s 5 -c 1 profiles it)
    split_conv_w2<<<dim3(1024, 5), 256>>>(conv_w[0], conv_w[1], conv_w[2], conv_w[3],
                                          conv_w[4], wc2);                       // 0
    split_x2<<<Nn, 256>>>(features, x2);                                         // 1
    split_mat<<<1024, 256>>>(fp_w, fpw3, 5120, 1);                               // 2
    split_mat<<<1024, 256>>>(wq, wq3, 1024, 1);                                  // 3
    split_mat<<<1024, 256>>>(wk, wk3, 1024, 1);                                  // 4

    // conv bank (fp16 2-term tensor GEMM) -> ms3 triple                         // 5
    conv_tc<<<dim3(8, 16, 5), 256, TC_SMEM>>>(x2, wc2, conv_b[0], conv_b[1], conv_b[2],
                                              conv_b[3], conv_b[4], ms3);

    split_mat<<<1024, 256>>>(wv, wv3, 1024, 1);                                  // 6
    split_mat<<<1024, 256>>>(wo, wo3, 1024, 1);                                  // 7
    split_mat<<<1024, 256>>>(gat_w, gw3, 1024, 1);                               // 8

    // fusion projection -> zpre (fp32)
    dense_tc<<<dim3(8, 16), 256, TC_SMEM>>>(ms3, fpw3, fp_b, zpre, nullptr, 15360, 0);

    // LN + GELU -> z3 triple
    ln_gelu_kernel<<<Nn, 256>>>(zpre, ln_g, ln_b, z3);

    // Q,K,V projections (q3/k3 triple, v fp32)
    dense_tc<<<dim3(8, 16), 256, TC_SMEM>>>(z3, wq3, bq, nullptr, q3, 3072, 0);
    dense_tc<<<dim3(8, 16), 256, TC_SMEM>>>(z3, wk3, bk, nullptr, k3, 3072, 1);
    dense_tc<<<dim3(8, 16), 256, TC_SMEM>>>(z3, wv3, bv, v, nullptr, 3072, 0);

    // attention: scores (TC) -> softmax (emits attn3) -> vT3 -> AV (TC)
    attn_qk<<<dim3(2, 2, 128), 256, TC_SMEM>>>(q3, k3, sc);
    softmax256<<<Bsz * HM * Tn, 256>>>(sc, attn3);
    vt3_kernel<<<128, 256>>>(v, vt3);
    attn_av<<<dim3(2, 128), 128, AV_SMEM>>>(attn3, vt3, ctx);

    // output projection -> att3 triple (feeds GAT GEMM only)
    split_mat<<<Nn, 256>>>(ctx, ctx3, 1024, 0);
    dense_tc<<<dim3(8, 16), 256, TC_SMEM>>>(ctx3, wo3, bo, nullptr, att3, 3072, 0);

    // GAT projection -> hg (fp32)
    dense_tc<<<dim3(8, 16), 256, TC_SMEM>>>(att3, gw3, gat_b, hg, nullptr, 3072, 0);

    // GAT logits + aggregate + residual
    e1e2_kernel<<<Nn, 256>>>(hg, ga1, ga2, e1, e2);
    e2max_kernel<<<HG, 256>>>(e2, e2m);
    gat_agg_kernel<<<dim3(Nn / TI, HG), 256>>>(hg, e1, e2, e2m, features, out);
}